// round 9
// baseline (speedup 1.0000x reference)
#include <cuda_runtime.h>
#include <cuda_bf16.h>
#include <cstdint>

#define BB 8
#define SS 2048
#define DD 512

// ---------------- device-global scratch (allocation-free) -------------------
__device__ __align__(16) __nv_bfloat16 g_xh[(size_t)BB * SS * DD];
__device__ __align__(16) __nv_bfloat16 g_xl[(size_t)BB * SS * DD];
__device__ __align__(16) __nv_bfloat16 g_wh[3 * DD * DD];
__device__ __align__(16) __nv_bfloat16 g_wl[3 * DD * DD];
__device__ __align__(16) __nv_bfloat16 g_qh[(size_t)BB * SS * DD];   // pre-scaled by 1/sqrt(S)
__device__ __align__(16) __nv_bfloat16 g_ql[(size_t)BB * SS * DD];
__device__ __align__(16) __nv_bfloat16 g_kh[(size_t)BB * SS * DD];   // compacted rows
__device__ __align__(16) __nv_bfloat16 g_kl[(size_t)BB * SS * DD];
__device__ __align__(16) __nv_bfloat16 g_vth[(size_t)BB * DD * SS];  // [b][d][slot]
__device__ __align__(16) __nv_bfloat16 g_vtl[(size_t)BB * DD * SS];
__device__ __align__(16) float         g_sc [(size_t)BB * SS * SS];
__device__ __align__(16) __nv_bfloat16 g_ph[(size_t)BB * SS * SS];
__device__ __align__(16) __nv_bfloat16 g_pl[(size_t)BB * SS * SS];
__device__ int g_slot[BB * SS];   // s -> compacted slot (-1 if masked)
__device__ int g_nvalid[BB];
__device__ int g_npad[BB];

// ---------------- PTX helpers ----------------------------------------------
static __device__ __forceinline__ uint32_t su32(const void* p) {
    return (uint32_t)__cvta_generic_to_shared(p);
}
__device__ __forceinline__ void cp16(uint32_t dst, const void* src) {
    asm volatile("cp.async.cg.shared.global [%0], [%1], 16;" :: "r"(dst), "l"(src));
}
__device__ __forceinline__ void cp_commit() {
    asm volatile("cp.async.commit_group;" ::: "memory");
}
template <int N>
__device__ __forceinline__ void cp_wait() {
    asm volatile("cp.async.wait_group %0;" :: "n"(N) : "memory");
}
__device__ __forceinline__ void ldm_x4(uint32_t addr, uint32_t r[4]) {
    asm volatile("ldmatrix.sync.aligned.m8n8.x4.shared.b16 {%0,%1,%2,%3}, [%4];"
                 : "=r"(r[0]), "=r"(r[1]), "=r"(r[2]), "=r"(r[3]) : "r"(addr));
}
__device__ __forceinline__ void mma_bf16(float c[4], const uint32_t a[4], const uint32_t b[2]) {
    asm volatile(
        "mma.sync.aligned.m16n8k16.row.col.f32.bf16.bf16.f32 "
        "{%0,%1,%2,%3}, {%4,%5,%6,%7}, {%8,%9}, {%0,%1,%2,%3};"
        : "+f"(c[0]), "+f"(c[1]), "+f"(c[2]), "+f"(c[3])
        : "r"(a[0]), "r"(a[1]), "r"(a[2]), "r"(a[3]), "r"(b[0]), "r"(b[1]));
}
__device__ __forceinline__ uint32_t pack_split(float a, float b) {
    __nv_bfloat162 t(__float2bfloat16(a), __float2bfloat16(b));
    return *reinterpret_cast<uint32_t*>(&t);
}
__device__ __forceinline__ float bfv(float a) {
    return __bfloat162float(__float2bfloat16(a));
}

// ---------------- 3-stage pipelined block GEMM, CTA 256x128 ------------------
// C(256x128) += (Ah+Al)*(Bh+Bl)^T (3-pass, pass-major). K%16==0.
// 8 warps as 4(m) x 2(n), warp tile 64x64.
// Stage = Ah(256x16) Al Bh(128x16) Bl, bf16 rows at 48B pitch.
#define PITCH 48
#define TILE_A_B 12288          // 256 * 48
#define TILE_B_B 6144           // 128 * 48
#define STAGE_B 36864           // 2*TILE_A_B + 2*TILE_B_B
#define NSTG 3
#define SMEM_BYTES (NSTG * STAGE_B)   // 110592

__device__ __forceinline__ void gemm_pipe(const __nv_bfloat16* __restrict__ Agh,
                                          const __nv_bfloat16* __restrict__ Agl,
                                          const __nv_bfloat16* __restrict__ Bgh,
                                          const __nv_bfloat16* __restrict__ Bgl,
                                          int K, int ldA, int ldB,
                                          char* smem, float acc[4][8][4]) {
    const int tid  = threadIdx.x;
    const int lane = tid & 31;
    const int w    = tid >> 5;
    const int wm   = w & 3;        // 4 m-positions x 64 rows
    const int wn   = w >> 2;       // 2 n-positions x 64 cols
    const int m0   = blockIdx.y * 256;
    const int n0   = blockIdx.x * 128;
    const uint32_t sbase = su32(smem);

#pragma unroll
    for (int mi = 0; mi < 4; mi++)
#pragma unroll
        for (int nj = 0; nj < 8; nj++)
#pragma unroll
            for (int e = 0; e < 4; e++) acc[mi][nj][e] = 0.0f;

    const int NK = K >> 4;
    const int rA = tid >> 1;          // A chunk row (first half)
    const int cA = tid & 1;           // 16B chunk within row

    const uint32_t offAf = (uint32_t)(wm * 64 + (lane & 15)) * PITCH + (lane >> 4) * 16;
    const uint32_t offBf = (uint32_t)(wn * 64 + (lane & 7) + ((lane >> 4) << 3)) * PITCH
                         + (((lane >> 3) & 1) << 4);

#define ISSUE(kidx, buf)                                                          \
    do {                                                                          \
        const int k0 = (kidx) << 4;                                               \
        uint32_t st = sbase + (buf) * STAGE_B;                                    \
        {                                                                         \
            size_t ga = (size_t)(m0 + rA) * ldA + k0 + cA * 8;                    \
            uint32_t da = st + rA * PITCH + cA * 16;                              \
            cp16(da,            Agh + ga);                                        \
            cp16(da + TILE_A_B, Agl + ga);                                        \
        }                                                                         \
        {                                                                         \
            size_t ga = (size_t)(m0 + rA + 128) * ldA + k0 + cA * 8;              \
            uint32_t da = st + (rA + 128) * PITCH + cA * 16;                      \
            cp16(da,            Agh + ga);                                        \
            cp16(da + TILE_A_B, Agl + ga);                                        \
        }                                                                         \
        {                                                                         \
            size_t gb = (size_t)(n0 + rA) * ldB + k0 + cA * 8;                    \
            uint32_t db = st + 2 * TILE_A_B + rA * PITCH + cA * 16;               \
            cp16(db,            Bgh + gb);                                        \
            cp16(db + TILE_B_B, Bgl + gb);                                        \
        }                                                                         \
        cp_commit();                                                              \
    } while (0)

    ISSUE(0, 0); ISSUE(1, 1);

    int rb = 0, wb = 2;
    for (int k = 0; k < NK; k++) {
        cp_wait<1>();
        __syncthreads();

        const uint32_t st = sbase + rb * STAGE_B;
        uint32_t ah[4][4], al[4][4];
#pragma unroll
        for (int mi = 0; mi < 4; mi++) {
            uint32_t o = offAf + (uint32_t)(mi * 16 * PITCH);
            ldm_x4(st + o, ah[mi]);
            ldm_x4(st + TILE_A_B + o, al[mi]);
        }
        uint32_t bh[8][2], bl[8][2];
#pragma unroll
        for (int nj4 = 0; nj4 < 4; nj4++) {
            uint32_t o = offBf + (uint32_t)(nj4 * 16 * PITCH);
            uint32_t t[4];
            ldm_x4(st + 2 * TILE_A_B + o, t);
            bh[2 * nj4][0] = t[0]; bh[2 * nj4][1] = t[1];
            bh[2 * nj4 + 1][0] = t[2]; bh[2 * nj4 + 1][1] = t[3];
            ldm_x4(st + 2 * TILE_A_B + TILE_B_B + o, t);
            bl[2 * nj4][0] = t[0]; bl[2 * nj4][1] = t[1];
            bl[2 * nj4 + 1][0] = t[2]; bl[2 * nj4 + 1][1] = t[3];
        }

        // pass-major (32 independent MMAs between accumulator reuses)
#pragma unroll
        for (int mi = 0; mi < 4; mi++)
#pragma unroll
            for (int nj = 0; nj < 8; nj++)
                mma_bf16(acc[mi][nj], ah[mi], bh[nj]);
#pragma unroll
        for (int mi = 0; mi < 4; mi++)
#pragma unroll
            for (int nj = 0; nj < 8; nj++)
                mma_bf16(acc[mi][nj], al[mi], bh[nj]);
#pragma unroll
        for (int mi = 0; mi < 4; mi++)
#pragma unroll
            for (int nj = 0; nj < 8; nj++)
                mma_bf16(acc[mi][nj], ah[mi], bl[nj]);

        if (k + 2 < NK) ISSUE(k + 2, wb);
        else            cp_commit();
        rb = (rb + 1 == NSTG) ? 0 : rb + 1;
        wb = (wb + 1 == NSTG) ? 0 : wb + 1;
    }
#undef ISSUE
}

// ---------------- epilogues --------------------------------------------------
__device__ __forceinline__ void store_acc_f32(float* __restrict__ C, int ldC,
                                              const float acc[4][8][4]) {
    const int lane = threadIdx.x & 31;
    const int w = threadIdx.x >> 5;
    const int wm = w & 3, wn = w >> 2;
    const int mb = blockIdx.y * 256 + wm * 64 + (lane >> 2);
    const int nb = blockIdx.x * 128 + wn * 64 + (lane & 3) * 2;
#pragma unroll
    for (int mi = 0; mi < 4; mi++) {
        int m = mb + mi * 16;
#pragma unroll
        for (int nj = 0; nj < 8; nj++) {
            int n = nb + nj * 8;
            *reinterpret_cast<float2*>(C + (size_t)m * ldC + n) =
                make_float2(acc[mi][nj][0], acc[mi][nj][1]);
            *reinterpret_cast<float2*>(C + (size_t)(m + 8) * ldC + n) =
                make_float2(acc[mi][nj][2], acc[mi][nj][3]);
        }
    }
}

__device__ __forceinline__ void store_acc_split(__nv_bfloat16* __restrict__ H,
                                                __nv_bfloat16* __restrict__ L,
                                                int ldC, const float acc[4][8][4],
                                                float scale) {
    const int lane = threadIdx.x & 31;
    const int w = threadIdx.x >> 5;
    const int wm = w & 3, wn = w >> 2;
    const int mb = blockIdx.y * 256 + wm * 64 + (lane >> 2);
    const int nb = blockIdx.x * 128 + wn * 64 + (lane & 3) * 2;
#pragma unroll
    for (int mi = 0; mi < 4; mi++) {
        int m = mb + mi * 16;
#pragma unroll
        for (int nj = 0; nj < 8; nj++) {
            int n = nb + nj * 8;
#pragma unroll
            for (int half = 0; half < 2; half++) {
                float a = acc[mi][nj][half * 2] * scale;
                float b = acc[mi][nj][half * 2 + 1] * scale;
                size_t idx = (size_t)(m + half * 8) * ldC + n;
                *reinterpret_cast<uint32_t*>(H + idx) = pack_split(a, b);
                *reinterpret_cast<uint32_t*>(L + idx) =
                    pack_split(a - bfv(a), b - bfv(b));
            }
        }
    }
}

// ---------------- kernels ----------------------------------------------------
__global__ void __launch_bounds__(256)
split_kernel(const float* __restrict__ src, __nv_bfloat16* __restrict__ h,
             __nv_bfloat16* __restrict__ l, int n4) {
    int i = blockIdx.x * blockDim.x + threadIdx.x;
    if (i >= n4) return;
    float4 v = reinterpret_cast<const float4*>(src)[i];
    reinterpret_cast<uint2*>(h)[i] = make_uint2(pack_split(v.x, v.y), pack_split(v.z, v.w));
    reinterpret_cast<uint2*>(l)[i] = make_uint2(pack_split(v.x - bfv(v.x), v.y - bfv(v.y)),
                                                pack_split(v.z - bfv(v.z), v.w - bfv(v.w)));
}

// per-batch compaction index (1 block per batch, 256 threads x 8 elems)
__global__ void __launch_bounds__(256)
build_index(const int* __restrict__ mask) {
    const int b = blockIdx.x;
    const int t = threadIdx.x;
    const int* m = mask + b * SS;
    const int base = t * 8;
    int loc[8], cnt = 0;
#pragma unroll
    for (int i = 0; i < 8; i++) { loc[i] = (m[base + i] != 0); cnt += loc[i]; }
    const int lane = t & 31, w = t >> 5;
    int v = cnt;
#pragma unroll
    for (int o = 1; o < 32; o <<= 1) {
        int u = __shfl_up_sync(0xffffffffu, v, o);
        if (lane >= o) v += u;
    }
    __shared__ int ws[8];
    if (lane == 31) ws[w] = v;
    __syncthreads();
    int wo = 0;
#pragma unroll
    for (int i = 0; i < 8; i++) if (i < w) wo += ws[i];
    int excl = wo + v - cnt;
#pragma unroll
    for (int i = 0; i < 8; i++) {
        g_slot[b * SS + base + i] = loc[i] ? excl : -1;
        excl += loc[i];
    }
    if (t == 255) {
        int tot = wo + v;
        g_nvalid[b] = tot;
        g_npad[b]   = (tot + 127) & ~127;
    }
}

// QKV: grid=(4, 64, 3). z: 0=Q(scaled), 1=K(compacted rows), 2=V(transposed+compacted)
__global__ void __launch_bounds__(256)
qkv_mm(int dummy) {
    extern __shared__ char smem[];
    const int z = blockIdx.z;
    float acc[4][8][4];
    gemm_pipe(g_xh, g_xl, g_wh + z * DD * DD, g_wl + z * DD * DD,
              DD, DD, DD, smem, acc);

    const int lane = threadIdx.x & 31;
    const int w = threadIdx.x >> 5;
    const int wm = w & 3, wn = w >> 2;
    const int mb = blockIdx.y * 256 + wm * 64 + (lane >> 2);
    const int nb = blockIdx.x * 128 + wn * 64 + (lane & 3) * 2;
    const int b = mb >> 11;

    if (z == 0) {
        store_acc_split(g_qh, g_ql, DD, acc, 0.0220970869120796101f);  // 1/sqrt(2048)
    } else if (z == 1) {
#pragma unroll
        for (int mi = 0; mi < 4; mi++) {
#pragma unroll
            for (int half = 0; half < 2; half++) {
                int s = (mb & 2047) + mi * 16 + half * 8;
                int slot = g_slot[b * SS + s];
                if (slot < 0) continue;
                size_t rowo = ((size_t)b * SS + slot) * DD;
#pragma unroll
                for (int nj = 0; nj < 8; nj++) {
                    float a = acc[mi][nj][half * 2], c = acc[mi][nj][half * 2 + 1];
                    *reinterpret_cast<uint32_t*>(g_kh + rowo + nb + nj * 8) =
                        pack_split(a, c);
                    *reinterpret_cast<uint32_t*>(g_kl + rowo + nb + nj * 8) =
                        pack_split(a - bfv(a), c - bfv(c));
                }
            }
        }
    } else {
        __nv_bfloat16* vh = g_vth + (size_t)b * DD * SS;
        __nv_bfloat16* vl = g_vtl + (size_t)b * DD * SS;
#pragma unroll
        for (int mi = 0; mi < 4; mi++) {
#pragma unroll
            for (int half = 0; half < 2; half++) {
                int s = (mb & 2047) + mi * 16 + half * 8;
                int slot = g_slot[b * SS + s];
                if (slot < 0) continue;
#pragma unroll
                for (int nj = 0; nj < 8; nj++) {
                    int d = nb + nj * 8;
                    float v0 = acc[mi][nj][half * 2];
                    float v1 = acc[mi][nj][half * 2 + 1];
                    vh[(size_t)d * SS + slot]       = __float2bfloat16(v0);
                    vl[(size_t)d * SS + slot]       = __float2bfloat16(v0 - bfv(v0));
                    vh[(size_t)(d + 1) * SS + slot] = __float2bfloat16(v1);
                    vl[(size_t)(d + 1) * SS + slot] = __float2bfloat16(v1 - bfv(v1));
                }
            }
        }
    }
}

// scores over compacted keys (Q pre-scaled): grid=(16,8,8); CTAs beyond npad exit
__global__ void __launch_bounds__(256)
scores_mm(int dummy) {
    extern __shared__ char smem[];
    const int b = blockIdx.z;
    const int npad = g_npad[b];
    if (blockIdx.x * 128 >= npad) return;
    const int nv = g_nvalid[b];

    float acc[4][8][4];
    gemm_pipe(g_qh + (size_t)b * SS * DD, g_ql + (size_t)b * SS * DD,
              g_kh + (size_t)b * SS * DD, g_kl + (size_t)b * SS * DD,
              DD, DD, DD, smem, acc);

    const int lane = threadIdx.x & 31;
    const int w = threadIdx.x >> 5;
    const int wm = w & 3, wn = w >> 2;
    const int mb = blockIdx.y * 256 + wm * 64 + (lane >> 2);
    const int nb = blockIdx.x * 128 + wn * 64 + (lane & 3) * 2;
    float* Scb = g_sc + (size_t)b * SS * SS;

#pragma unroll
    for (int nj = 0; nj < 8; nj++) {
        int n = nb + nj * 8;
#pragma unroll
        for (int mi = 0; mi < 4; mi++) {
            int m = mb + mi * 16;
            float r0 = (n     < nv) ? acc[mi][nj][0] : -1e30f;
            float r1 = (n + 1 < nv) ? acc[mi][nj][1] : -1e30f;
            float r2 = (n     < nv) ? acc[mi][nj][2] : -1e30f;
            float r3 = (n + 1 < nv) ? acc[mi][nj][3] : -1e30f;
            *reinterpret_cast<float2*>(Scb + (size_t)m * SS + n) = make_float2(r0, r1);
            *reinterpret_cast<float2*>(Scb + (size_t)(m + 8) * SS + n) = make_float2(r2, r3);
        }
    }
}

// softmax over compacted width: one block per (b,row)
__global__ void __launch_bounds__(256)
softmax_kernel() {
    __shared__ float red[8];
    const int b = blockIdx.x >> 11;
    const int W = g_npad[b];
    const size_t base = (size_t)blockIdx.x * SS;
    const float* p = g_sc + base;
    const int tid = threadIdx.x;

    float4 v[2];
    int ni = 0;
    float mx = -1e38f;
    for (int x = tid * 4; x < W; x += 1024) {
        v[ni] = *reinterpret_cast<const float4*>(p + x);
        mx = fmaxf(mx, fmaxf(fmaxf(v[ni].x, v[ni].y), fmaxf(v[ni].z, v[ni].w)));
        ni++;
    }
#pragma unroll
    for (int o = 16; o > 0; o >>= 1) mx = fmaxf(mx, __shfl_xor_sync(0xffffffffu, mx, o));
    if ((tid & 31) == 0) red[tid >> 5] = mx;
    __syncthreads();
    mx = red[0];
#pragma unroll
    for (int wi = 1; wi < 8; wi++) mx = fmaxf(mx, red[wi]);

    float sum = 0.0f;
    for (int i = 0; i < ni; i++) {
        v[i].x = __expf(v[i].x - mx);
        v[i].y = __expf(v[i].y - mx);
        v[i].z = __expf(v[i].z - mx);
        v[i].w = __expf(v[i].w - mx);
        sum += (v[i].x + v[i].y) + (v[i].z + v[i].w);
    }
#pragma unroll
    for (int o = 16; o > 0; o >>= 1) sum += __shfl_xor_sync(0xffffffffu, sum, o);
    __syncthreads();
    if ((tid & 31) == 0) red[tid >> 5] = sum;
    __syncthreads();
    sum = 0.0f;
#pragma unroll
    for (int wi = 0; wi < 8; wi++) sum += red[wi];

    const float rinv = 1.0f / sum;
    int i = 0;
    for (int x = tid * 4; x < W; x += 1024, i++) {
        float px = v[i].x * rinv, py = v[i].y * rinv;
        float pz = v[i].z * rinv, pw = v[i].w * rinv;
        *reinterpret_cast<uint2*>(g_ph + base + x) =
            make_uint2(pack_split(px, py), pack_split(pz, pw));
        *reinterpret_cast<uint2*>(g_pl + base + x) =
            make_uint2(pack_split(px - bfv(px), py - bfv(py)),
                       pack_split(pz - bfv(pz), pw - bfv(pw)));
    }
}

// PV over compacted K-dim: grid=(4,8,8)
__global__ void __launch_bounds__(256)
pv_mm(float* __restrict__ out) {
    extern __shared__ char smem[];
    const int b = blockIdx.z;
    const int W = g_npad[b];
    float acc[4][8][4];
    gemm_pipe(g_ph + (size_t)b * SS * SS, g_pl + (size_t)b * SS * SS,
              g_vth + (size_t)b * DD * SS, g_vtl + (size_t)b * DD * SS,
              W, SS, SS, smem, acc);
    store_acc_f32(out + (size_t)b * SS * DD, DD, acc);
}

// ---------------------------------------------------------------------------
extern "C" void kernel_launch(void* const* d_in, const int* in_sizes, int n_in,
                              void* d_out, int out_size) {
    const float* X    = (const float*)d_in[0];
    const int*   mask = (const int*)  d_in[1];
    const float* Wq   = (const float*)d_in[2];
    const float* Wk   = (const float*)d_in[3];
    const float* Wv   = (const float*)d_in[4];
    float* out = (float*)d_out;

    static bool attr_done = false;
    if (!attr_done) {
        cudaFuncSetAttribute(qkv_mm,    cudaFuncAttributeMaxDynamicSharedMemorySize, SMEM_BYTES);
        cudaFuncSetAttribute(scores_mm, cudaFuncAttributeMaxDynamicSharedMemorySize, SMEM_BYTES);
        cudaFuncSetAttribute(pv_mm,     cudaFuncAttributeMaxDynamicSharedMemorySize, SMEM_BYTES);
        attr_done = true;
    }

    __nv_bfloat16 *xh, *xl, *wh, *wl;
    cudaGetSymbolAddress((void**)&xh, g_xh);
    cudaGetSymbolAddress((void**)&xl, g_xl);
    cudaGetSymbolAddress((void**)&wh, g_wh);
    cudaGetSymbolAddress((void**)&wl, g_wl);

    const int nX4 = (BB * SS * DD) / 4;
    const int nW4 = (DD * DD) / 4;
    split_kernel<<<(nX4 + 255) / 256, 256>>>(X, xh, xl, nX4);
    split_kernel<<<(nW4 + 255) / 256, 256>>>(Wq, wh,            wl,            nW4);
    split_kernel<<<(nW4 + 255) / 256, 256>>>(Wk, wh + DD * DD,  wl + DD * DD,  nW4);
    split_kernel<<<(nW4 + 255) / 256, 256>>>(Wv, wh + 2*DD*DD,  wl + 2*DD*DD,  nW4);
    build_index<<<BB, 256>>>(mask);

    dim3 blk(256);
    qkv_mm<<<dim3(DD / 128, (BB * SS) / 256, 3), blk, SMEM_BYTES>>>(0);
    scores_mm<<<dim3(SS / 128, SS / 256, BB), blk, SMEM_BYTES>>>(0);
    softmax_kernel<<<BB * SS, 256>>>();
    pv_mm<<<dim3(DD / 128, SS / 256, BB), blk, SMEM_BYTES>>>(out);
}

// round 10
// speedup vs baseline: 1.1591x; 1.1591x over previous
#include <cuda_runtime.h>
#include <cuda_bf16.h>
#include <cstdint>

#define BB 8
#define SS 2048
#define DD 512

// ---------------- device-global scratch (allocation-free) -------------------
__device__ __align__(16) __nv_bfloat16 g_xh[(size_t)BB * SS * DD];
__device__ __align__(16) __nv_bfloat16 g_xl[(size_t)BB * SS * DD];
__device__ __align__(16) __nv_bfloat16 g_xch[(size_t)BB * SS * DD];  // compacted X
__device__ __align__(16) __nv_bfloat16 g_xcl[(size_t)BB * SS * DD];
__device__ __align__(16) __nv_bfloat16 g_wh[3 * DD * DD];
__device__ __align__(16) __nv_bfloat16 g_wl[3 * DD * DD];
__device__ __align__(16) __nv_bfloat16 g_qh[(size_t)BB * SS * DD];   // pre-scaled by 1/sqrt(S)
__device__ __align__(16) __nv_bfloat16 g_ql[(size_t)BB * SS * DD];
__device__ __align__(16) __nv_bfloat16 g_kh[(size_t)BB * SS * DD];   // compacted rows
__device__ __align__(16) __nv_bfloat16 g_kl[(size_t)BB * SS * DD];
__device__ __align__(16) __nv_bfloat16 g_vth[(size_t)BB * DD * SS];  // [b][d][slot]
__device__ __align__(16) __nv_bfloat16 g_vtl[(size_t)BB * DD * SS];
__device__ __align__(16) float         g_sc [(size_t)BB * SS * SS];
__device__ __align__(16) __nv_bfloat16 g_ph[(size_t)BB * SS * SS];
__device__ __align__(16) __nv_bfloat16 g_pl[(size_t)BB * SS * SS];
__device__ int g_slot[BB * SS];   // s -> compacted slot (-1 if masked)
__device__ int g_nvalid[BB];
__device__ int g_npad[BB];

// ---------------- PTX helpers ----------------------------------------------
static __device__ __forceinline__ uint32_t su32(const void* p) {
    return (uint32_t)__cvta_generic_to_shared(p);
}
__device__ __forceinline__ void cp16(uint32_t dst, const void* src) {
    asm volatile("cp.async.cg.shared.global [%0], [%1], 16;" :: "r"(dst), "l"(src));
}
__device__ __forceinline__ void cp_commit() {
    asm volatile("cp.async.commit_group;" ::: "memory");
}
template <int N>
__device__ __forceinline__ void cp_wait() {
    asm volatile("cp.async.wait_group %0;" :: "n"(N) : "memory");
}
__device__ __forceinline__ void ldm_x4(uint32_t addr, uint32_t r[4]) {
    asm volatile("ldmatrix.sync.aligned.m8n8.x4.shared.b16 {%0,%1,%2,%3}, [%4];"
                 : "=r"(r[0]), "=r"(r[1]), "=r"(r[2]), "=r"(r[3]) : "r"(addr));
}
__device__ __forceinline__ void mma_bf16(float c[4], const uint32_t a[4], const uint32_t b[2]) {
    asm volatile(
        "mma.sync.aligned.m16n8k16.row.col.f32.bf16.bf16.f32 "
        "{%0,%1,%2,%3}, {%4,%5,%6,%7}, {%8,%9}, {%0,%1,%2,%3};"
        : "+f"(c[0]), "+f"(c[1]), "+f"(c[2]), "+f"(c[3])
        : "r"(a[0]), "r"(a[1]), "r"(a[2]), "r"(a[3]), "r"(b[0]), "r"(b[1]));
}
__device__ __forceinline__ uint32_t pack_split(float a, float b) {
    __nv_bfloat162 t(__float2bfloat16(a), __float2bfloat16(b));
    return *reinterpret_cast<uint32_t*>(&t);
}
__device__ __forceinline__ float bfv(float a) {
    return __bfloat162float(__float2bfloat16(a));
}

// ---------------- 4-stage pipelined block GEMM (K-chunk 16) ------------------
// C(128x128) += (Ah+Al)*(Bh+Bl)^T (3-pass, pass-major). K%16==0.
// Stage = {Ah,Al,Bh,Bl} tiles of 128x16 bf16 at 48B row pitch.
#define PITCH 48
#define TILE_B 6144            // 128 * 48
#define STAGE_B 24576          // 4 * TILE_B
#define NSTG 4
#define SMEM_BYTES (NSTG * STAGE_B)   // 98304

__device__ __forceinline__ void gemm_pipe(const __nv_bfloat16* __restrict__ Agh,
                                          const __nv_bfloat16* __restrict__ Agl,
                                          const __nv_bfloat16* __restrict__ Bgh,
                                          const __nv_bfloat16* __restrict__ Bgl,
                                          int K, int ldA, int ldB,
                                          int m0, int n0,
                                          char* smem, float acc[2][8][4]) {
    const int tid  = threadIdx.x;
    const int lane = tid & 31;
    const int w    = tid >> 5;
    const int wm   = w & 3;
    const int wn   = w >> 2;
    const uint32_t sbase = su32(smem);

#pragma unroll
    for (int mi = 0; mi < 2; mi++)
#pragma unroll
        for (int nj = 0; nj < 8; nj++)
#pragma unroll
            for (int e = 0; e < 4; e++) acc[mi][nj][e] = 0.0f;

    const int NK = K >> 4;
    const int r0 = tid >> 1;          // row 0..127
    const int c0 = tid & 1;           // 16B chunk 0..1

    const uint32_t offA = (uint32_t)(wm * 32 + (lane & 15)) * PITCH + ((lane >> 4) * 8) * 2;
    const uint32_t offB = (uint32_t)(wn * 64 + (lane & 7) + ((lane >> 4) << 3)) * PITCH
                        + (((lane >> 3) & 1) << 3) * 2;

#define ISSUE(kidx)                                                               \
    do {                                                                          \
        const int k0 = (kidx) << 4;                                               \
        uint32_t st = sbase + ((kidx) & (NSTG - 1)) * STAGE_B;                    \
        size_t ga = (size_t)(m0 + r0) * ldA + k0 + c0 * 8;                        \
        size_t gb = (size_t)(n0 + r0) * ldB + k0 + c0 * 8;                        \
        uint32_t da = st + r0 * PITCH + c0 * 16;                                  \
        cp16(da,              Agh + ga);                                          \
        cp16(da + TILE_B,     Agl + ga);                                          \
        cp16(da + 2 * TILE_B, Bgh + gb);                                          \
        cp16(da + 3 * TILE_B, Bgl + gb);                                          \
        cp_commit();                                                              \
    } while (0)

    ISSUE(0); ISSUE(1); ISSUE(2);

    for (int k = 0; k < NK; k++) {
        cp_wait<2>();
        __syncthreads();

        const uint32_t st  = sbase + (k & (NSTG - 1)) * STAGE_B;
        uint32_t ah[2][4], al[2][4];
#pragma unroll
        for (int mi = 0; mi < 2; mi++) {
            ldm_x4(st + offA + (uint32_t)(mi * 16 * PITCH), ah[mi]);
            ldm_x4(st + TILE_B + offA + (uint32_t)(mi * 16 * PITCH), al[mi]);
        }
        uint32_t bh[8][2], bl[8][2];
#pragma unroll
        for (int nj4 = 0; nj4 < 4; nj4++) {
            uint32_t o = offB + (uint32_t)(nj4 * 16 * PITCH);
            uint32_t t[4];
            ldm_x4(st + 2 * TILE_B + o, t);
            bh[2 * nj4][0] = t[0]; bh[2 * nj4][1] = t[1];
            bh[2 * nj4 + 1][0] = t[2]; bh[2 * nj4 + 1][1] = t[3];
            ldm_x4(st + 3 * TILE_B + o, t);
            bl[2 * nj4][0] = t[0]; bl[2 * nj4][1] = t[1];
            bl[2 * nj4 + 1][0] = t[2]; bl[2 * nj4 + 1][1] = t[3];
        }

#pragma unroll
        for (int mi = 0; mi < 2; mi++)
#pragma unroll
            for (int nj = 0; nj < 8; nj++)
                mma_bf16(acc[mi][nj], ah[mi], bh[nj]);
#pragma unroll
        for (int mi = 0; mi < 2; mi++)
#pragma unroll
            for (int nj = 0; nj < 8; nj++)
                mma_bf16(acc[mi][nj], ah[mi], bl[nj]);
#pragma unroll
        for (int mi = 0; mi < 2; mi++)
#pragma unroll
            for (int nj = 0; nj < 8; nj++)
                mma_bf16(acc[mi][nj], al[mi], bh[nj]);

        if (k + 3 < NK) ISSUE(k + 3);
        else            cp_commit();
    }
#undef ISSUE
}

// ---------------- epilogues --------------------------------------------------
__device__ __forceinline__ void store_acc_f32(float* __restrict__ C, int ldC,
                                              int m0, int n0,
                                              const float acc[2][8][4]) {
    const int lane = threadIdx.x & 31;
    const int w = threadIdx.x >> 5;
    const int wm = w & 3, wn = w >> 2;
    const int mb = m0 + wm * 32 + (lane >> 2);
    const int nb = n0 + wn * 64 + (lane & 3) * 2;
#pragma unroll
    for (int mi = 0; mi < 2; mi++) {
        int m = mb + mi * 16;
#pragma unroll
        for (int nj = 0; nj < 8; nj++) {
            int n = nb + nj * 8;
            *reinterpret_cast<float2*>(C + (size_t)m * ldC + n) =
                make_float2(acc[mi][nj][0], acc[mi][nj][1]);
            *reinterpret_cast<float2*>(C + (size_t)(m + 8) * ldC + n) =
                make_float2(acc[mi][nj][2], acc[mi][nj][3]);
        }
    }
}

__device__ __forceinline__ void store_acc_split(__nv_bfloat16* __restrict__ H,
                                                __nv_bfloat16* __restrict__ L,
                                                int ldC, int m0, int n0,
                                                const float acc[2][8][4],
                                                float scale) {
    const int lane = threadIdx.x & 31;
    const int w = threadIdx.x >> 5;
    const int wm = w & 3, wn = w >> 2;
    const int mb = m0 + wm * 32 + (lane >> 2);
    const int nb = n0 + wn * 64 + (lane & 3) * 2;
#pragma unroll
    for (int mi = 0; mi < 2; mi++) {
        int m = mb + mi * 16;
#pragma unroll
        for (int nj = 0; nj < 8; nj++) {
            int n = nb + nj * 8;
#pragma unroll
            for (int half = 0; half < 2; half++) {
                float a = acc[mi][nj][half * 2] * scale;
                float b = acc[mi][nj][half * 2 + 1] * scale;
                size_t idx = (size_t)(m + half * 8) * ldC + n;
                *reinterpret_cast<uint32_t*>(H + idx) = pack_split(a, b);
                *reinterpret_cast<uint32_t*>(L + idx) =
                    pack_split(a - bfv(a), b - bfv(b));
            }
        }
    }
}

// ---------------- kernels ----------------------------------------------------
__global__ void __launch_bounds__(256)
split_kernel(const float* __restrict__ src, __nv_bfloat16* __restrict__ h,
             __nv_bfloat16* __restrict__ l, int n4) {
    int i = blockIdx.x * blockDim.x + threadIdx.x;
    if (i >= n4) return;
    float4 v = reinterpret_cast<const float4*>(src)[i];
    reinterpret_cast<uint2*>(h)[i] = make_uint2(pack_split(v.x, v.y), pack_split(v.z, v.w));
    reinterpret_cast<uint2*>(l)[i] = make_uint2(pack_split(v.x - bfv(v.x), v.y - bfv(v.y)),
                                                pack_split(v.z - bfv(v.z), v.w - bfv(v.w)));
}

// per-batch compaction index (1 block per batch, 256 threads x 8 elems)
__global__ void __launch_bounds__(256)
build_index(const int* __restrict__ mask) {
    const int b = blockIdx.x;
    const int t = threadIdx.x;
    const int* m = mask + b * SS;
    const int base = t * 8;
    int loc[8], cnt = 0;
#pragma unroll
    for (int i = 0; i < 8; i++) { loc[i] = (m[base + i] != 0); cnt += loc[i]; }
    const int lane = t & 31, w = t >> 5;
    int v = cnt;
#pragma unroll
    for (int o = 1; o < 32; o <<= 1) {
        int u = __shfl_up_sync(0xffffffffu, v, o);
        if (lane >= o) v += u;
    }
    __shared__ int ws[8];
    if (lane == 31) ws[w] = v;
    __syncthreads();
    int wo = 0;
#pragma unroll
    for (int i = 0; i < 8; i++) if (i < w) wo += ws[i];
    int excl = wo + v - cnt;
#pragma unroll
    for (int i = 0; i < 8; i++) {
        g_slot[b * SS + base + i] = loc[i] ? excl : -1;
        excl += loc[i];
    }
    if (t == 255) {
        int tot = wo + v;
        g_nvalid[b] = tot;
        g_npad[b]   = (tot + 127) & ~127;
    }
}

// gather compacted X rows: 8 rows per block (32 lanes per row)
__global__ void __launch_bounds__(256)
gather_x() {
    const int r = blockIdx.x * 8 + (threadIdx.x >> 5);
    const int lane = threadIdx.x & 31;
    const int slot = g_slot[r];
    if (slot < 0) return;
    const int b = r >> 11;
    const uint4* sh = reinterpret_cast<const uint4*>(g_xh + (size_t)r * DD);
    const uint4* sl = reinterpret_cast<const uint4*>(g_xl + (size_t)r * DD);
    uint4* dh = reinterpret_cast<uint4*>(g_xch + ((size_t)b * SS + slot) * DD);
    uint4* dl = reinterpret_cast<uint4*>(g_xcl + ((size_t)b * SS + slot) * DD);
    dh[lane] = sh[lane]; dh[lane + 32] = sh[lane + 32];
    dl[lane] = sl[lane]; dl[lane + 32] = sl[lane + 32];
}

// Q projection (all rows, pre-scaled): grid=(4, 128)
__global__ void __launch_bounds__(256, 2)
q_mm(int dummy) {
    extern __shared__ char smem[];
    const int m0 = blockIdx.y * 128, n0 = blockIdx.x * 128;
    float acc[2][8][4];
    gemm_pipe(g_xh, g_xl, g_wh, g_wl, DD, DD, DD, m0, n0, smem, acc);
    store_acc_split(g_qh, g_ql, DD, m0, n0, acc, 0.0220970869120796101f); // 1/sqrt(2048)
}

// K/V projections over compacted rows: grid=(4, 16, 16); z = b*2 + which
__global__ void __launch_bounds__(256, 2)
kv_mm(int dummy) {
    extern __shared__ char smem[];
    const int b = blockIdx.z >> 1;
    const int which = blockIdx.z & 1;          // 0=K, 1=V
    if (blockIdx.y * 128 >= g_npad[b]) return;

    const int m0 = blockIdx.y * 128;           // within-batch compacted row
    const int n0 = blockIdx.x * 128;
    const __nv_bfloat16* Wh = g_wh + (1 + which) * DD * DD;
    const __nv_bfloat16* Wl = g_wl + (1 + which) * DD * DD;
    float acc[2][8][4];
    gemm_pipe(g_xch + (size_t)b * SS * DD, g_xcl + (size_t)b * SS * DD,
              Wh, Wl, DD, DD, DD, m0, n0, smem, acc);

    const int lane = threadIdx.x & 31;
    const int w = threadIdx.x >> 5;
    const int wm = w & 3, wn = w >> 2;
    const int mb = m0 + wm * 32 + (lane >> 2);
    const int nb = n0 + wn * 64 + (lane & 3) * 2;

    if (which == 0) {
        // K: direct compacted rows
        store_acc_split(g_kh + (size_t)b * SS * DD, g_kl + (size_t)b * SS * DD,
                        DD, m0, n0, acc, 1.0f);
    } else {
        // V: transposed into [d][slot]
        __nv_bfloat16* vh = g_vth + (size_t)b * DD * SS;
        __nv_bfloat16* vl = g_vtl + (size_t)b * DD * SS;
#pragma unroll
        for (int mi = 0; mi < 2; mi++) {
#pragma unroll
            for (int half = 0; half < 2; half++) {
                int s = mb + mi * 16 + half * 8;
#pragma unroll
                for (int nj = 0; nj < 8; nj++) {
                    int d = nb + nj * 8;
                    float v0 = acc[mi][nj][half * 2];
                    float v1 = acc[mi][nj][half * 2 + 1];
                    vh[(size_t)d * SS + s]       = __float2bfloat16(v0);
                    vl[(size_t)d * SS + s]       = __float2bfloat16(v0 - bfv(v0));
                    vh[(size_t)(d + 1) * SS + s] = __float2bfloat16(v1);
                    vl[(size_t)(d + 1) * SS + s] = __float2bfloat16(v1 - bfv(v1));
                }
            }
        }
    }
}

// scores over compacted keys (Q pre-scaled): grid=(16,16,8); CTAs beyond npad exit
__global__ void __launch_bounds__(256, 2)
scores_mm(int dummy) {
    extern __shared__ char smem[];
    const int b = blockIdx.z;
    const int npad = g_npad[b];
    if (blockIdx.x * 128 >= npad) return;
    const int nv = g_nvalid[b];
    const int m0 = blockIdx.y * 128, n0 = blockIdx.x * 128;

    float acc[2][8][4];
    gemm_pipe(g_qh + (size_t)b * SS * DD, g_ql + (size_t)b * SS * DD,
              g_kh + (size_t)b * SS * DD, g_kl + (size_t)b * SS * DD,
              DD, DD, DD, m0, n0, smem, acc);

    const int lane = threadIdx.x & 31;
    const int w = threadIdx.x >> 5;
    const int wm = w & 3, wn = w >> 2;
    const int mb = m0 + wm * 32 + (lane >> 2);
    const int nb = n0 + wn * 64 + (lane & 3) * 2;
    float* Scb = g_sc + (size_t)b * SS * SS;

#pragma unroll
    for (int nj = 0; nj < 8; nj++) {
        int n = nb + nj * 8;
#pragma unroll
        for (int mi = 0; mi < 2; mi++) {
            int m = mb + mi * 16;
            float r0 = (n     < nv) ? acc[mi][nj][0] : -1e30f;
            float r1 = (n + 1 < nv) ? acc[mi][nj][1] : -1e30f;
            float r2 = (n     < nv) ? acc[mi][nj][2] : -1e30f;
            float r3 = (n + 1 < nv) ? acc[mi][nj][3] : -1e30f;
            *reinterpret_cast<float2*>(Scb + (size_t)m * SS + n) = make_float2(r0, r1);
            *reinterpret_cast<float2*>(Scb + (size_t)(m + 8) * SS + n) = make_float2(r2, r3);
        }
    }
}

// softmax over compacted width: one block per (b,row)
__global__ void __launch_bounds__(256)
softmax_kernel() {
    __shared__ float red[8];
    const int b = blockIdx.x >> 11;
    const int W = g_npad[b];
    const size_t base = (size_t)blockIdx.x * SS;
    const float* p = g_sc + base;
    const int tid = threadIdx.x;

    float4 v[2];
    int ni = 0;
    float mx = -1e38f;
    for (int x = tid * 4; x < W; x += 1024) {
        v[ni] = *reinterpret_cast<const float4*>(p + x);
        mx = fmaxf(mx, fmaxf(fmaxf(v[ni].x, v[ni].y), fmaxf(v[ni].z, v[ni].w)));
        ni++;
    }
#pragma unroll
    for (int o = 16; o > 0; o >>= 1) mx = fmaxf(mx, __shfl_xor_sync(0xffffffffu, mx, o));
    if ((tid & 31) == 0) red[tid >> 5] = mx;
    __syncthreads();
    mx = red[0];
#pragma unroll
    for (int wi = 1; wi < 8; wi++) mx = fmaxf(mx, red[wi]);

    float sum = 0.0f;
    for (int i = 0; i < ni; i++) {
        v[i].x = __expf(v[i].x - mx);
        v[i].y = __expf(v[i].y - mx);
        v[i].z = __expf(v[i].z - mx);
        v[i].w = __expf(v[i].w - mx);
        sum += (v[i].x + v[i].y) + (v[i].z + v[i].w);
    }
#pragma unroll
    for (int o = 16; o > 0; o >>= 1) sum += __shfl_xor_sync(0xffffffffu, sum, o);
    __syncthreads();
    if ((tid & 31) == 0) red[tid >> 5] = sum;
    __syncthreads();
    sum = 0.0f;
#pragma unroll
    for (int wi = 0; wi < 8; wi++) sum += red[wi];

    const float rinv = 1.0f / sum;
    int i = 0;
    for (int x = tid * 4; x < W; x += 1024, i++) {
        float px = v[i].x * rinv, py = v[i].y * rinv;
        float pz = v[i].z * rinv, pw = v[i].w * rinv;
        *reinterpret_cast<uint2*>(g_ph + base + x) =
            make_uint2(pack_split(px, py), pack_split(pz, pw));
        *reinterpret_cast<uint2*>(g_pl + base + x) =
            make_uint2(pack_split(px - bfv(px), py - bfv(py)),
                       pack_split(pz - bfv(pz), pw - bfv(pw)));
    }
}

// PV over compacted K-dim: grid=(4,16,8)
__global__ void __launch_bounds__(256, 2)
pv_mm(float* __restrict__ out) {
    extern __shared__ char smem[];
    const int b = blockIdx.z;
    const int W = g_npad[b];
    const int m0 = blockIdx.y * 128, n0 = blockIdx.x * 128;
    float acc[2][8][4];
    gemm_pipe(g_ph + (size_t)b * SS * SS, g_pl + (size_t)b * SS * SS,
              g_vth + (size_t)b * DD * SS, g_vtl + (size_t)b * DD * SS,
              W, SS, SS, m0, n0, smem, acc);
    store_acc_f32(out + (size_t)b * SS * DD, DD, m0, n0, acc);
}

// ---------------------------------------------------------------------------
extern "C" void kernel_launch(void* const* d_in, const int* in_sizes, int n_in,
                              void* d_out, int out_size) {
    const float* X    = (const float*)d_in[0];
    const int*   mask = (const int*)  d_in[1];
    const float* Wq   = (const float*)d_in[2];
    const float* Wk   = (const float*)d_in[3];
    const float* Wv   = (const float*)d_in[4];
    float* out = (float*)d_out;

    static bool attr_done = false;
    if (!attr_done) {
        cudaFuncSetAttribute(q_mm,      cudaFuncAttributeMaxDynamicSharedMemorySize, SMEM_BYTES);
        cudaFuncSetAttribute(kv_mm,     cudaFuncAttributeMaxDynamicSharedMemorySize, SMEM_BYTES);
        cudaFuncSetAttribute(scores_mm, cudaFuncAttributeMaxDynamicSharedMemorySize, SMEM_BYTES);
        cudaFuncSetAttribute(pv_mm,     cudaFuncAttributeMaxDynamicSharedMemorySize, SMEM_BYTES);
        attr_done = true;
    }

    __nv_bfloat16 *xh, *xl, *wh, *wl;
    cudaGetSymbolAddress((void**)&xh, g_xh);
    cudaGetSymbolAddress((void**)&xl, g_xl);
    cudaGetSymbolAddress((void**)&wh, g_wh);
    cudaGetSymbolAddress((void**)&wl, g_wl);

    const int nX4 = (BB * SS * DD) / 4;
    const int nW4 = (DD * DD) / 4;
    split_kernel<<<(nX4 + 255) / 256, 256>>>(X, xh, xl, nX4);
    split_kernel<<<(nW4 + 255) / 256, 256>>>(Wq, wh,            wl,            nW4);
    split_kernel<<<(nW4 + 255) / 256, 256>>>(Wk, wh + DD * DD,  wl + DD * DD,  nW4);
    split_kernel<<<(nW4 + 255) / 256, 256>>>(Wv, wh + 2*DD*DD,  wl + 2*DD*DD,  nW4);
    build_index<<<BB, 256>>>(mask);
    gather_x<<<BB * SS / 8, 256>>>();

    dim3 blk(256);
    q_mm<<<dim3(DD / 128, (BB * SS) / 128), blk, SMEM_BYTES>>>(0);
    kv_mm<<<dim3(DD / 128, SS / 128, 2 * BB), blk, SMEM_BYTES>>>(0);
    scores_mm<<<dim3(SS / 128, SS / 128, BB), blk, SMEM_BYTES>>>(0);
    softmax_kernel<<<BB * SS, 256>>>();
    pv_mm<<<dim3(DD / 128, SS / 128, BB), blk, SMEM_BYTES>>>(out);
}

// round 11
// speedup vs baseline: 1.3325x; 1.1496x over previous
#include <cuda_runtime.h>
#include <cuda_bf16.h>
#include <cuda_fp16.h>
#include <cstdint>

#define BB 8
#define SS 2048
#define DD 512

// ---------------- device-global scratch (allocation-free) -------------------
__device__ __align__(16) __nv_bfloat16 g_xh[(size_t)BB * SS * DD];
__device__ __align__(16) __nv_bfloat16 g_xl[(size_t)BB * SS * DD];
__device__ __align__(16) __nv_bfloat16 g_xch[(size_t)BB * SS * DD];  // compacted X
__device__ __align__(16) __nv_bfloat16 g_xcl[(size_t)BB * SS * DD];
__device__ __align__(16) __nv_bfloat16 g_wh[3 * DD * DD];
__device__ __align__(16) __nv_bfloat16 g_wl[3 * DD * DD];
__device__ __align__(16) __half        g_q16[(size_t)BB * SS * DD];  // Q, plain fp16 (unscaled)
__device__ __align__(16) __half        g_k16h[(size_t)BB * SS * DD]; // K fp16 split, compacted
__device__ __align__(16) __half        g_k16l[(size_t)BB * SS * DD];
__device__ __align__(16) __nv_bfloat16 g_vth[(size_t)BB * DD * SS];  // [b][d][slot]
__device__ __align__(16) __nv_bfloat16 g_vtl[(size_t)BB * DD * SS];
__device__ __align__(16) float         g_sc [(size_t)BB * SS * SS];
__device__ __align__(16) __nv_bfloat16 g_ph[(size_t)BB * SS * SS];
__device__ __align__(16) __nv_bfloat16 g_pl[(size_t)BB * SS * SS];
__device__ int g_slot[BB * SS];
__device__ int g_nvalid[BB];
__device__ int g_npad[BB];

// ---------------- PTX helpers ----------------------------------------------
static __device__ __forceinline__ uint32_t su32(const void* p) {
    return (uint32_t)__cvta_generic_to_shared(p);
}
__device__ __forceinline__ void cp16(uint32_t dst, const void* src) {
    asm volatile("cp.async.cg.shared.global [%0], [%1], 16;" :: "r"(dst), "l"(src));
}
__device__ __forceinline__ void cp_commit() {
    asm volatile("cp.async.commit_group;" ::: "memory");
}
template <int N>
__device__ __forceinline__ void cp_wait() {
    asm volatile("cp.async.wait_group %0;" :: "n"(N) : "memory");
}
__device__ __forceinline__ void ldm_x4(uint32_t addr, uint32_t r[4]) {
    asm volatile("ldmatrix.sync.aligned.m8n8.x4.shared.b16 {%0,%1,%2,%3}, [%4];"
                 : "=r"(r[0]), "=r"(r[1]), "=r"(r[2]), "=r"(r[3]) : "r"(addr));
}
__device__ __forceinline__ void mma_bf16(float c[4], const uint32_t a[4], const uint32_t b[2]) {
    asm volatile(
        "mma.sync.aligned.m16n8k16.row.col.f32.bf16.bf16.f32 "
        "{%0,%1,%2,%3}, {%4,%5,%6,%7}, {%8,%9}, {%0,%1,%2,%3};"
        : "+f"(c[0]), "+f"(c[1]), "+f"(c[2]), "+f"(c[3])
        : "r"(a[0]), "r"(a[1]), "r"(a[2]), "r"(a[3]), "r"(b[0]), "r"(b[1]));
}
__device__ __forceinline__ void mma_f16(float c[4], const uint32_t a[4], const uint32_t b[2]) {
    asm volatile(
        "mma.sync.aligned.m16n8k16.row.col.f32.f16.f16.f32 "
        "{%0,%1,%2,%3}, {%4,%5,%6,%7}, {%8,%9}, {%0,%1,%2,%3};"
        : "+f"(c[0]), "+f"(c[1]), "+f"(c[2]), "+f"(c[3])
        : "r"(a[0]), "r"(a[1]), "r"(a[2]), "r"(a[3]), "r"(b[0]), "r"(b[1]));
}
__device__ __forceinline__ uint32_t pack_split(float a, float b) {
    __nv_bfloat162 t(__float2bfloat16(a), __float2bfloat16(b));
    return *reinterpret_cast<uint32_t*>(&t);
}
__device__ __forceinline__ uint32_t pack_h2(float a, float b) {
    __half2 t(__float2half(a), __float2half(b));
    return *reinterpret_cast<uint32_t*>(&t);
}
__device__ __forceinline__ float bfv(float a) {
    return __bfloat162float(__float2bfloat16(a));
}
__device__ __forceinline__ float hfv(float a) {
    return __half2float(__float2half(a));
}

// ---------------- 4-stage pipelined block GEMM (bf16 3-pass) -----------------
#define PITCH 48
#define TILE_B 6144            // 128 * 48
#define STAGE_B 24576          // 4 * TILE_B
#define NSTG 4
#define SMEM_BYTES (NSTG * STAGE_B)   // 98304

__device__ __forceinline__ void gemm_pipe(const __nv_bfloat16* __restrict__ Agh,
                                          const __nv_bfloat16* __restrict__ Agl,
                                          const __nv_bfloat16* __restrict__ Bgh,
                                          const __nv_bfloat16* __restrict__ Bgl,
                                          int K, int ldA, int ldB,
                                          int m0, int n0,
                                          char* smem, float acc[2][8][4]) {
    const int tid  = threadIdx.x;
    const int lane = tid & 31;
    const int w    = tid >> 5;
    const int wm   = w & 3;
    const int wn   = w >> 2;
    const uint32_t sbase = su32(smem);

#pragma unroll
    for (int mi = 0; mi < 2; mi++)
#pragma unroll
        for (int nj = 0; nj < 8; nj++)
#pragma unroll
            for (int e = 0; e < 4; e++) acc[mi][nj][e] = 0.0f;

    const int NK = K >> 4;
    const int r0 = tid >> 1;
    const int c0 = tid & 1;

    const uint32_t offA = (uint32_t)(wm * 32 + (lane & 15)) * PITCH + ((lane >> 4) * 8) * 2;
    const uint32_t offB = (uint32_t)(wn * 64 + (lane & 7) + ((lane >> 4) << 3)) * PITCH
                        + (((lane >> 3) & 1) << 3) * 2;

#define ISSUE(kidx)                                                               \
    do {                                                                          \
        const int k0 = (kidx) << 4;                                               \
        uint32_t st = sbase + ((kidx) & (NSTG - 1)) * STAGE_B;                    \
        size_t ga = (size_t)(m0 + r0) * ldA + k0 + c0 * 8;                        \
        size_t gb = (size_t)(n0 + r0) * ldB + k0 + c0 * 8;                        \
        uint32_t da = st + r0 * PITCH + c0 * 16;                                  \
        cp16(da,              Agh + ga);                                          \
        cp16(da + TILE_B,     Agl + ga);                                          \
        cp16(da + 2 * TILE_B, Bgh + gb);                                          \
        cp16(da + 3 * TILE_B, Bgl + gb);                                          \
        cp_commit();                                                              \
    } while (0)

    ISSUE(0); ISSUE(1); ISSUE(2);

    for (int k = 0; k < NK; k++) {
        cp_wait<2>();
        __syncthreads();

        const uint32_t st  = sbase + (k & (NSTG - 1)) * STAGE_B;
        uint32_t ah[2][4], al[2][4];
#pragma unroll
        for (int mi = 0; mi < 2; mi++) {
            ldm_x4(st + offA + (uint32_t)(mi * 16 * PITCH), ah[mi]);
            ldm_x4(st + TILE_B + offA + (uint32_t)(mi * 16 * PITCH), al[mi]);
        }
        uint32_t bh[8][2], bl[8][2];
#pragma unroll
        for (int nj4 = 0; nj4 < 4; nj4++) {
            uint32_t o = offB + (uint32_t)(nj4 * 16 * PITCH);
            uint32_t t[4];
            ldm_x4(st + 2 * TILE_B + o, t);
            bh[2 * nj4][0] = t[0]; bh[2 * nj4][1] = t[1];
            bh[2 * nj4 + 1][0] = t[2]; bh[2 * nj4 + 1][1] = t[3];
            ldm_x4(st + 3 * TILE_B + o, t);
            bl[2 * nj4][0] = t[0]; bl[2 * nj4][1] = t[1];
            bl[2 * nj4 + 1][0] = t[2]; bl[2 * nj4 + 1][1] = t[3];
        }

#pragma unroll
        for (int mi = 0; mi < 2; mi++)
#pragma unroll
            for (int nj = 0; nj < 8; nj++)
                mma_bf16(acc[mi][nj], ah[mi], bh[nj]);
#pragma unroll
        for (int mi = 0; mi < 2; mi++)
#pragma unroll
            for (int nj = 0; nj < 8; nj++)
                mma_bf16(acc[mi][nj], ah[mi], bl[nj]);
#pragma unroll
        for (int mi = 0; mi < 2; mi++)
#pragma unroll
            for (int nj = 0; nj < 8; nj++)
                mma_bf16(acc[mi][nj], al[mi], bh[nj]);

        if (k + 3 < NK) ISSUE(k + 3);
        else            cp_commit();
    }
#undef ISSUE
}

// ---------------- fp16 2-pass GEMM (scores): C = A16 * (Bh+Bl)^T -------------
#define STAGE2_B 18432          // 3 * TILE_B
#define SMEM2_BYTES (NSTG * STAGE2_B)   // 73728

__device__ __forceinline__ void gemm_pipe_f16(const __half* __restrict__ Ag,
                                              const __half* __restrict__ Bgh,
                                              const __half* __restrict__ Bgl,
                                              int K, int ldA, int ldB,
                                              int m0, int n0,
                                              char* smem, float acc[2][8][4]) {
    const int tid  = threadIdx.x;
    const int lane = tid & 31;
    const int w    = tid >> 5;
    const int wm   = w & 3;
    const int wn   = w >> 2;
    const uint32_t sbase = su32(smem);

#pragma unroll
    for (int mi = 0; mi < 2; mi++)
#pragma unroll
        for (int nj = 0; nj < 8; nj++)
#pragma unroll
            for (int e = 0; e < 4; e++) acc[mi][nj][e] = 0.0f;

    const int NK = K >> 4;
    const int r0 = tid >> 1;
    const int c0 = tid & 1;

    const uint32_t offA = (uint32_t)(wm * 32 + (lane & 15)) * PITCH + ((lane >> 4) * 8) * 2;
    const uint32_t offB = (uint32_t)(wn * 64 + (lane & 7) + ((lane >> 4) << 3)) * PITCH
                        + (((lane >> 3) & 1) << 3) * 2;

#define ISSUE2(kidx)                                                              \
    do {                                                                          \
        const int k0 = (kidx) << 4;                                               \
        uint32_t st = sbase + ((kidx) & (NSTG - 1)) * STAGE2_B;                   \
        size_t ga = (size_t)(m0 + r0) * ldA + k0 + c0 * 8;                        \
        size_t gb = (size_t)(n0 + r0) * ldB + k0 + c0 * 8;                        \
        uint32_t da = st + r0 * PITCH + c0 * 16;                                  \
        cp16(da,              Ag  + ga);                                          \
        cp16(da + TILE_B,     Bgh + gb);                                          \
        cp16(da + 2 * TILE_B, Bgl + gb);                                          \
        cp_commit();                                                              \
    } while (0)

    ISSUE2(0); ISSUE2(1); ISSUE2(2);

    for (int k = 0; k < NK; k++) {
        cp_wait<2>();
        __syncthreads();

        const uint32_t st  = sbase + (k & (NSTG - 1)) * STAGE2_B;
        uint32_t ah[2][4];
#pragma unroll
        for (int mi = 0; mi < 2; mi++)
            ldm_x4(st + offA + (uint32_t)(mi * 16 * PITCH), ah[mi]);
        uint32_t bh[8][2], bl[8][2];
#pragma unroll
        for (int nj4 = 0; nj4 < 4; nj4++) {
            uint32_t o = offB + (uint32_t)(nj4 * 16 * PITCH);
            uint32_t t[4];
            ldm_x4(st + TILE_B + o, t);
            bh[2 * nj4][0] = t[0]; bh[2 * nj4][1] = t[1];
            bh[2 * nj4 + 1][0] = t[2]; bh[2 * nj4 + 1][1] = t[3];
            ldm_x4(st + 2 * TILE_B + o, t);
            bl[2 * nj4][0] = t[0]; bl[2 * nj4][1] = t[1];
            bl[2 * nj4 + 1][0] = t[2]; bl[2 * nj4 + 1][1] = t[3];
        }

#pragma unroll
        for (int mi = 0; mi < 2; mi++)
#pragma unroll
            for (int nj = 0; nj < 8; nj++)
                mma_f16(acc[mi][nj], ah[mi], bh[nj]);
#pragma unroll
        for (int mi = 0; mi < 2; mi++)
#pragma unroll
            for (int nj = 0; nj < 8; nj++)
                mma_f16(acc[mi][nj], ah[mi], bl[nj]);

        if (k + 3 < NK) ISSUE2(k + 3);
        else            cp_commit();
    }
#undef ISSUE2
}

// ---------------- epilogues --------------------------------------------------
__device__ __forceinline__ void store_acc_f32(float* __restrict__ C, int ldC,
                                              int m0, int n0,
                                              const float acc[2][8][4]) {
    const int lane = threadIdx.x & 31;
    const int w = threadIdx.x >> 5;
    const int wm = w & 3, wn = w >> 2;
    const int mb = m0 + wm * 32 + (lane >> 2);
    const int nb = n0 + wn * 64 + (lane & 3) * 2;
#pragma unroll
    for (int mi = 0; mi < 2; mi++) {
        int m = mb + mi * 16;
#pragma unroll
        for (int nj = 0; nj < 8; nj++) {
            int n = nb + nj * 8;
            *reinterpret_cast<float2*>(C + (size_t)m * ldC + n) =
                make_float2(acc[mi][nj][0], acc[mi][nj][1]);
            *reinterpret_cast<float2*>(C + (size_t)(m + 8) * ldC + n) =
                make_float2(acc[mi][nj][2], acc[mi][nj][3]);
        }
    }
}

// ---------------- kernels ----------------------------------------------------
__global__ void __launch_bounds__(256)
split_kernel(const float* __restrict__ src, __nv_bfloat16* __restrict__ h,
             __nv_bfloat16* __restrict__ l, int n4) {
    int i = blockIdx.x * blockDim.x + threadIdx.x;
    if (i >= n4) return;
    float4 v = reinterpret_cast<const float4*>(src)[i];
    reinterpret_cast<uint2*>(h)[i] = make_uint2(pack_split(v.x, v.y), pack_split(v.z, v.w));
    reinterpret_cast<uint2*>(l)[i] = make_uint2(pack_split(v.x - bfv(v.x), v.y - bfv(v.y)),
                                                pack_split(v.z - bfv(v.z), v.w - bfv(v.w)));
}

__global__ void __launch_bounds__(256)
build_index(const int* __restrict__ mask) {
    const int b = blockIdx.x;
    const int t = threadIdx.x;
    const int* m = mask + b * SS;
    const int base = t * 8;
    int loc[8], cnt = 0;
#pragma unroll
    for (int i = 0; i < 8; i++) { loc[i] = (m[base + i] != 0); cnt += loc[i]; }
    const int lane = t & 31, w = t >> 5;
    int v = cnt;
#pragma unroll
    for (int o = 1; o < 32; o <<= 1) {
        int u = __shfl_up_sync(0xffffffffu, v, o);
        if (lane >= o) v += u;
    }
    __shared__ int ws[8];
    if (lane == 31) ws[w] = v;
    __syncthreads();
    int wo = 0;
#pragma unroll
    for (int i = 0; i < 8; i++) if (i < w) wo += ws[i];
    int excl = wo + v - cnt;
#pragma unroll
    for (int i = 0; i < 8; i++) {
        g_slot[b * SS + base + i] = loc[i] ? excl : -1;
        excl += loc[i];
    }
    if (t == 255) {
        int tot = wo + v;
        g_nvalid[b] = tot;
        g_npad[b]   = (tot + 127) & ~127;
    }
}

__global__ void __launch_bounds__(256)
gather_x() {
    const int r = blockIdx.x * 8 + (threadIdx.x >> 5);
    const int lane = threadIdx.x & 31;
    const int slot = g_slot[r];
    if (slot < 0) return;
    const int b = r >> 11;
    const uint4* sh = reinterpret_cast<const uint4*>(g_xh + (size_t)r * DD);
    const uint4* sl = reinterpret_cast<const uint4*>(g_xl + (size_t)r * DD);
    uint4* dh = reinterpret_cast<uint4*>(g_xch + ((size_t)b * SS + slot) * DD);
    uint4* dl = reinterpret_cast<uint4*>(g_xcl + ((size_t)b * SS + slot) * DD);
    dh[lane] = sh[lane]; dh[lane + 32] = sh[lane + 32];
    dl[lane] = sl[lane]; dl[lane + 32] = sl[lane + 32];
}

// merged QKV: grid=(4,128,3). z=0: Q (fp16, all rows); z=1: K (fp16 split,
// compacted); z=2: V (bf16 split, transposed+compacted)
__global__ void __launch_bounds__(256, 2)
qkv_mm(int dummy) {
    extern __shared__ char smem[];
    const int z = blockIdx.z;
    int m0, b = 0;
    const __nv_bfloat16 *Ah, *Al;
    if (z == 0) {
        m0 = blockIdx.y * 128;
        Ah = g_xh; Al = g_xl;
    } else {
        b = blockIdx.y >> 4;
        m0 = (blockIdx.y & 15) * 128;
        if (m0 >= g_npad[b]) return;
        Ah = g_xch + (size_t)b * SS * DD;
        Al = g_xcl + (size_t)b * SS * DD;
    }
    const int n0 = blockIdx.x * 128;
    const int wsel = (z == 0) ? 0 : (1 + (z & 1));   // z=1 -> Wk(1)? careful below
    // z mapping: 0->Wq, 1->Wk, 2->Wv
    const __nv_bfloat16* Wh = g_wh + z * DD * DD;
    const __nv_bfloat16* Wl = g_wl + z * DD * DD;
    (void)wsel;

    float acc[2][8][4];
    gemm_pipe(Ah, Al, Wh, Wl, DD, DD, DD, m0, n0, smem, acc);

    const int lane = threadIdx.x & 31;
    const int w = threadIdx.x >> 5;
    const int wm = w & 3, wn = w >> 2;
    const int mb = m0 + wm * 32 + (lane >> 2);
    const int nb = n0 + wn * 64 + (lane & 3) * 2;

    if (z == 0) {
        // Q: plain fp16, unscaled (1/sqrt(S) applied in scores epilogue)
#pragma unroll
        for (int mi = 0; mi < 2; mi++) {
            int m = mb + mi * 16;
#pragma unroll
            for (int nj = 0; nj < 8; nj++) {
                int n = nb + nj * 8;
                *reinterpret_cast<uint32_t*>(g_q16 + (size_t)m * DD + n) =
                    pack_h2(acc[mi][nj][0], acc[mi][nj][1]);
                *reinterpret_cast<uint32_t*>(g_q16 + (size_t)(m + 8) * DD + n) =
                    pack_h2(acc[mi][nj][2], acc[mi][nj][3]);
            }
        }
    } else if (z == 1) {
        // K: fp16 split, compacted rows
        __half* kh = g_k16h + (size_t)b * SS * DD;
        __half* kl = g_k16l + (size_t)b * SS * DD;
#pragma unroll
        for (int mi = 0; mi < 2; mi++) {
#pragma unroll
            for (int half = 0; half < 2; half++) {
                int m = mb + mi * 16 + half * 8;
#pragma unroll
                for (int nj = 0; nj < 8; nj++) {
                    int n = nb + nj * 8;
                    float a = acc[mi][nj][half * 2], c = acc[mi][nj][half * 2 + 1];
                    *reinterpret_cast<uint32_t*>(kh + (size_t)m * DD + n) = pack_h2(a, c);
                    *reinterpret_cast<uint32_t*>(kl + (size_t)m * DD + n) =
                        pack_h2(a - hfv(a), c - hfv(c));
                }
            }
        }
    } else {
        // V: bf16 split, transposed
        __nv_bfloat16* vh = g_vth + (size_t)b * DD * SS;
        __nv_bfloat16* vl = g_vtl + (size_t)b * DD * SS;
#pragma unroll
        for (int mi = 0; mi < 2; mi++) {
#pragma unroll
            for (int half = 0; half < 2; half++) {
                int s = mb + mi * 16 + half * 8;
#pragma unroll
                for (int nj = 0; nj < 8; nj++) {
                    int d = nb + nj * 8;
                    float v0 = acc[mi][nj][half * 2];
                    float v1 = acc[mi][nj][half * 2 + 1];
                    vh[(size_t)d * SS + s]       = __float2bfloat16(v0);
                    vl[(size_t)d * SS + s]       = __float2bfloat16(v0 - bfv(v0));
                    vh[(size_t)(d + 1) * SS + s] = __float2bfloat16(v1);
                    vl[(size_t)(d + 1) * SS + s] = __float2bfloat16(v1 - bfv(v1));
                }
            }
        }
    }
}

// scores: fp16 2-pass over compacted keys. grid=(16,16,8)
__global__ void __launch_bounds__(256, 2)
scores_mm(int dummy) {
    extern __shared__ char smem[];
    const int b = blockIdx.z;
    const int npad = g_npad[b];
    if (blockIdx.x * 128 >= npad) return;
    const int nv = g_nvalid[b];
    const int m0 = blockIdx.y * 128, n0 = blockIdx.x * 128;

    float acc[2][8][4];
    gemm_pipe_f16(g_q16 + (size_t)b * SS * DD,
                  g_k16h + (size_t)b * SS * DD, g_k16l + (size_t)b * SS * DD,
                  DD, DD, DD, m0, n0, smem, acc);

    const int lane = threadIdx.x & 31;
    const int w = threadIdx.x >> 5;
    const int wm = w & 3, wn = w >> 2;
    const int mb = m0 + wm * 32 + (lane >> 2);
    const int nb = n0 + wn * 64 + (lane & 3) * 2;
    const float inv_scale = 0.0220970869120796101f;  // 1/sqrt(2048)
    float* Scb = g_sc + (size_t)b * SS * SS;

#pragma unroll
    for (int nj = 0; nj < 8; nj++) {
        int n = nb + nj * 8;
#pragma unroll
        for (int mi = 0; mi < 2; mi++) {
            int m = mb + mi * 16;
            float r0 = (n     < nv) ? acc[mi][nj][0] * inv_scale : -1e30f;
            float r1 = (n + 1 < nv) ? acc[mi][nj][1] * inv_scale : -1e30f;
            float r2 = (n     < nv) ? acc[mi][nj][2] * inv_scale : -1e30f;
            float r3 = (n + 1 < nv) ? acc[mi][nj][3] * inv_scale : -1e30f;
            *reinterpret_cast<float2*>(Scb + (size_t)m * SS + n) = make_float2(r0, r1);
            *reinterpret_cast<float2*>(Scb + (size_t)(m + 8) * SS + n) = make_float2(r2, r3);
        }
    }
}

// softmax over compacted width: one block per (b,row)
__global__ void __launch_bounds__(256)
softmax_kernel() {
    __shared__ float red[8];
    const int b = blockIdx.x >> 11;
    const int W = g_npad[b];
    const size_t base = (size_t)blockIdx.x * SS;
    const float* p = g_sc + base;
    const int tid = threadIdx.x;

    float4 v[2];
    int ni = 0;
    float mx = -1e38f;
    for (int x = tid * 4; x < W; x += 1024) {
        v[ni] = *reinterpret_cast<const float4*>(p + x);
        mx = fmaxf(mx, fmaxf(fmaxf(v[ni].x, v[ni].y), fmaxf(v[ni].z, v[ni].w)));
        ni++;
    }
#pragma unroll
    for (int o = 16; o > 0; o >>= 1) mx = fmaxf(mx, __shfl_xor_sync(0xffffffffu, mx, o));
    if ((tid & 31) == 0) red[tid >> 5] = mx;
    __syncthreads();
    mx = red[0];
#pragma unroll
    for (int wi = 1; wi < 8; wi++) mx = fmaxf(mx, red[wi]);

    float sum = 0.0f;
    for (int i = 0; i < ni; i++) {
        v[i].x = __expf(v[i].x - mx);
        v[i].y = __expf(v[i].y - mx);
        v[i].z = __expf(v[i].z - mx);
        v[i].w = __expf(v[i].w - mx);
        sum += (v[i].x + v[i].y) + (v[i].z + v[i].w);
    }
#pragma unroll
    for (int o = 16; o > 0; o >>= 1) sum += __shfl_xor_sync(0xffffffffu, sum, o);
    __syncthreads();
    if ((tid & 31) == 0) red[tid >> 5] = sum;
    __syncthreads();
    sum = 0.0f;
#pragma unroll
    for (int wi = 0; wi < 8; wi++) sum += red[wi];

    const float rinv = 1.0f / sum;
    int i = 0;
    for (int x = tid * 4; x < W; x += 1024, i++) {
        float px = v[i].x * rinv, py = v[i].y * rinv;
        float pz = v[i].z * rinv, pw = v[i].w * rinv;
        *reinterpret_cast<uint2*>(g_ph + base + x) =
            make_uint2(pack_split(px, py), pack_split(pz, pw));
        *reinterpret_cast<uint2*>(g_pl + base + x) =
            make_uint2(pack_split(px - bfv(px), py - bfv(py)),
                       pack_split(pz - bfv(pz), pw - bfv(pw)));
    }
}

// PV over compacted K-dim: grid=(4,16,8)
__global__ void __launch_bounds__(256, 2)
pv_mm(float* __restrict__ out) {
    extern __shared__ char smem[];
    const int b = blockIdx.z;
    const int W = g_npad[b];
    const int m0 = blockIdx.y * 128, n0 = blockIdx.x * 128;
    float acc[2][8][4];
    gemm_pipe(g_ph + (size_t)b * SS * SS, g_pl + (size_t)b * SS * SS,
              g_vth + (size_t)b * DD * SS, g_vtl + (size_t)b * DD * SS,
              W, SS, SS, m0, n0, smem, acc);
    store_acc_f32(out + (size_t)b * SS * DD, DD, m0, n0, acc);
}

// ---------------------------------------------------------------------------
extern "C" void kernel_launch(void* const* d_in, const int* in_sizes, int n_in,
                              void* d_out, int out_size) {
    const float* X    = (const float*)d_in[0];
    const int*   mask = (const int*)  d_in[1];
    const float* Wq   = (const float*)d_in[2];
    const float* Wk   = (const float*)d_in[3];
    const float* Wv   = (const float*)d_in[4];
    float* out = (float*)d_out;

    static bool attr_done = false;
    if (!attr_done) {
        cudaFuncSetAttribute(qkv_mm,    cudaFuncAttributeMaxDynamicSharedMemorySize, SMEM_BYTES);
        cudaFuncSetAttribute(scores_mm, cudaFuncAttributeMaxDynamicSharedMemorySize, SMEM2_BYTES);
        cudaFuncSetAttribute(pv_mm,     cudaFuncAttributeMaxDynamicSharedMemorySize, SMEM_BYTES);
        attr_done = true;
    }

    __nv_bfloat16 *xh, *xl, *wh, *wl;
    cudaGetSymbolAddress((void**)&xh, g_xh);
    cudaGetSymbolAddress((void**)&xl, g_xl);
    cudaGetSymbolAddress((void**)&wh, g_wh);
    cudaGetSymbolAddress((void**)&wl, g_wl);

    const int nX4 = (BB * SS * DD) / 4;
    const int nW4 = (DD * DD) / 4;
    split_kernel<<<(nX4 + 255) / 256, 256>>>(X, xh, xl, nX4);
    split_kernel<<<(nW4 + 255) / 256, 256>>>(Wq, wh,            wl,            nW4);
    split_kernel<<<(nW4 + 255) / 256, 256>>>(Wk, wh + DD * DD,  wl + DD * DD,  nW4);
    split_kernel<<<(nW4 + 255) / 256, 256>>>(Wv, wh + 2*DD*DD,  wl + 2*DD*DD,  nW4);
    build_index<<<BB, 256>>>(mask);
    gather_x<<<BB * SS / 8, 256>>>();

    dim3 blk(256);
    qkv_mm<<<dim3(DD / 128, 128, 3), blk, SMEM_BYTES>>>(0);
    scores_mm<<<dim3(SS / 128, SS / 128, BB), blk, SMEM2_BYTES>>>(0);
    softmax_kernel<<<BB * SS, 256>>>();
    pv_mm<<<dim3(DD / 128, SS / 128, BB), blk, SMEM_BYTES>>>(out);
}

// round 12
// speedup vs baseline: 1.6102x; 1.2084x over previous
#include <cuda_runtime.h>
#include <cuda_bf16.h>
#include <cuda_fp16.h>
#include <cstdint>

#define BB 8
#define SS 2048
#define DD 512

// ---------------- device-global scratch (allocation-free, zero-init) --------
__device__ __align__(16) __half g_x16 [(size_t)BB * SS * DD];  // X plain fp16
__device__ __align__(16) __half g_x16c[(size_t)BB * SS * DD];  // compacted X
__device__ __align__(16) __half g_w16h[3 * DD * DD];           // W fp16 split
__device__ __align__(16) __half g_w16l[3 * DD * DD];
__device__ __align__(16) __half g_q16 [(size_t)BB * SS * DD];  // Q plain fp16 (unscaled)
__device__ __align__(16) __half g_k16h[(size_t)BB * SS * DD];  // K fp16 split, compacted
__device__ __align__(16) __half g_k16l[(size_t)BB * SS * DD];
__device__ __align__(16) __half g_vt16h[(size_t)BB * DD * SS]; // V^T fp16 split [b][d][slot]
__device__ __align__(16) __half g_vt16l[(size_t)BB * DD * SS];
__device__ __align__(16) float  g_sc [(size_t)BB * SS * SS];
__device__ __align__(16) __half g_p16[(size_t)BB * SS * SS];   // P plain fp16
__device__ int g_slot[BB * SS];
__device__ int g_nvalid[BB];
__device__ int g_npad[BB];

// ---------------- PTX helpers ----------------------------------------------
static __device__ __forceinline__ uint32_t su32(const void* p) {
    return (uint32_t)__cvta_generic_to_shared(p);
}
__device__ __forceinline__ void cp16(uint32_t dst, const void* src) {
    asm volatile("cp.async.cg.shared.global [%0], [%1], 16;" :: "r"(dst), "l"(src));
}
__device__ __forceinline__ void cp_commit() {
    asm volatile("cp.async.commit_group;" ::: "memory");
}
template <int N>
__device__ __forceinline__ void cp_wait() {
    asm volatile("cp.async.wait_group %0;" :: "n"(N) : "memory");
}
__device__ __forceinline__ void ldm_x4(uint32_t addr, uint32_t r[4]) {
    asm volatile("ldmatrix.sync.aligned.m8n8.x4.shared.b16 {%0,%1,%2,%3}, [%4];"
                 : "=r"(r[0]), "=r"(r[1]), "=r"(r[2]), "=r"(r[3]) : "r"(addr));
}
__device__ __forceinline__ void mma_f16(float c[4], const uint32_t a[4], const uint32_t b[2]) {
    asm volatile(
        "mma.sync.aligned.m16n8k16.row.col.f32.f16.f16.f32 "
        "{%0,%1,%2,%3}, {%4,%5,%6,%7}, {%8,%9}, {%0,%1,%2,%3};"
        : "+f"(c[0]), "+f"(c[1]), "+f"(c[2]), "+f"(c[3])
        : "r"(a[0]), "r"(a[1]), "r"(a[2]), "r"(a[3]), "r"(b[0]), "r"(b[1]));
}
__device__ __forceinline__ uint32_t pack_h2(float a, float b) {
    __half2 t(__float2half(a), __float2half(b));
    return *reinterpret_cast<uint32_t*>(&t);
}
__device__ __forceinline__ float hfv(float a) {
    return __half2float(__float2half(a));
}

// ---------------- fp16 2-pass pipelined GEMM: C = A16 * (Bh+Bl)^T -----------
// A:[M,K] ldA plain fp16; B:[N,K] ldB fp16 split. K%16==0.
// 4 stages x {A, Bh, Bl} tiles of 128x16 fp16 at 48B pitch.
#define PITCH 48
#define TILE_B 6144            // 128 * 48
#define STAGE_B 18432          // 3 * TILE_B
#define NSTG 4
#define SMEM_BYTES (NSTG * STAGE_B)   // 73728

__device__ __forceinline__ void gemm_pipe_f16(const __half* __restrict__ Ag,
                                              const __half* __restrict__ Bgh,
                                              const __half* __restrict__ Bgl,
                                              int K, int ldA, int ldB,
                                              int m0, int n0,
                                              char* smem, float acc[2][8][4]) {
    const int tid  = threadIdx.x;
    const int lane = tid & 31;
    const int w    = tid >> 5;
    const int wm   = w & 3;
    const int wn   = w >> 2;
    const uint32_t sbase = su32(smem);

#pragma unroll
    for (int mi = 0; mi < 2; mi++)
#pragma unroll
        for (int nj = 0; nj < 8; nj++)
#pragma unroll
            for (int e = 0; e < 4; e++) acc[mi][nj][e] = 0.0f;

    const int NK = K >> 4;
    const int r0 = tid >> 1;
    const int c0 = tid & 1;

    const uint32_t offA = (uint32_t)(wm * 32 + (lane & 15)) * PITCH + ((lane >> 4) * 8) * 2;
    const uint32_t offB = (uint32_t)(wn * 64 + (lane & 7) + ((lane >> 4) << 3)) * PITCH
                        + (((lane >> 3) & 1) << 3) * 2;

#define ISSUE(kidx)                                                               \
    do {                                                                          \
        const int k0 = (kidx) << 4;                                               \
        uint32_t st = sbase + ((kidx) & (NSTG - 1)) * STAGE_B;                    \
        size_t ga = (size_t)(m0 + r0) * ldA + k0 + c0 * 8;                        \
        size_t gb = (size_t)(n0 + r0) * ldB + k0 + c0 * 8;                        \
        uint32_t da = st + r0 * PITCH + c0 * 16;                                  \
        cp16(da,              Ag  + ga);                                          \
        cp16(da + TILE_B,     Bgh + gb);                                          \
        cp16(da + 2 * TILE_B, Bgl + gb);                                          \
        cp_commit();                                                              \
    } while (0)

    ISSUE(0); ISSUE(1); ISSUE(2);

    for (int k = 0; k < NK; k++) {
        cp_wait<2>();
        __syncthreads();

        const uint32_t st  = sbase + (k & (NSTG - 1)) * STAGE_B;
        uint32_t ah[2][4];
#pragma unroll
        for (int mi = 0; mi < 2; mi++)
            ldm_x4(st + offA + (uint32_t)(mi * 16 * PITCH), ah[mi]);
        uint32_t bh[8][2], bl[8][2];
#pragma unroll
        for (int nj4 = 0; nj4 < 4; nj4++) {
            uint32_t o = offB + (uint32_t)(nj4 * 16 * PITCH);
            uint32_t t[4];
            ldm_x4(st + TILE_B + o, t);
            bh[2 * nj4][0] = t[0]; bh[2 * nj4][1] = t[1];
            bh[2 * nj4 + 1][0] = t[2]; bh[2 * nj4 + 1][1] = t[3];
            ldm_x4(st + 2 * TILE_B + o, t);
            bl[2 * nj4][0] = t[0]; bl[2 * nj4][1] = t[1];
            bl[2 * nj4 + 1][0] = t[2]; bl[2 * nj4 + 1][1] = t[3];
        }

#pragma unroll
        for (int mi = 0; mi < 2; mi++)
#pragma unroll
            for (int nj = 0; nj < 8; nj++)
                mma_f16(acc[mi][nj], ah[mi], bh[nj]);
#pragma unroll
        for (int mi = 0; mi < 2; mi++)
#pragma unroll
            for (int nj = 0; nj < 8; nj++)
                mma_f16(acc[mi][nj], ah[mi], bl[nj]);

        if (k + 3 < NK) ISSUE(k + 3);
        else            cp_commit();
    }
#undef ISSUE
}

// ---------------- kernels ----------------------------------------------------
// X -> plain fp16
__global__ void __launch_bounds__(256)
split_plain(const float* __restrict__ src, __half* __restrict__ dst, int n4) {
    int i = blockIdx.x * blockDim.x + threadIdx.x;
    if (i >= n4) return;
    float4 v = reinterpret_cast<const float4*>(src)[i];
    reinterpret_cast<uint2*>(dst)[i] = make_uint2(pack_h2(v.x, v.y), pack_h2(v.z, v.w));
}

// W -> fp16 split
__global__ void __launch_bounds__(256)
split_f16(const float* __restrict__ src, __half* __restrict__ h,
          __half* __restrict__ l, int n4) {
    int i = blockIdx.x * blockDim.x + threadIdx.x;
    if (i >= n4) return;
    float4 v = reinterpret_cast<const float4*>(src)[i];
    reinterpret_cast<uint2*>(h)[i] = make_uint2(pack_h2(v.x, v.y), pack_h2(v.z, v.w));
    reinterpret_cast<uint2*>(l)[i] =
        make_uint2(pack_h2(v.x - hfv(v.x), v.y - hfv(v.y)),
                   pack_h2(v.z - hfv(v.z), v.w - hfv(v.w)));
}

__global__ void __launch_bounds__(256)
build_index(const int* __restrict__ mask) {
    const int b = blockIdx.x;
    const int t = threadIdx.x;
    const int* m = mask + b * SS;
    const int base = t * 8;
    int loc[8], cnt = 0;
#pragma unroll
    for (int i = 0; i < 8; i++) { loc[i] = (m[base + i] != 0); cnt += loc[i]; }
    const int lane = t & 31, w = t >> 5;
    int v = cnt;
#pragma unroll
    for (int o = 1; o < 32; o <<= 1) {
        int u = __shfl_up_sync(0xffffffffu, v, o);
        if (lane >= o) v += u;
    }
    __shared__ int ws[8];
    if (lane == 31) ws[w] = v;
    __syncthreads();
    int wo = 0;
#pragma unroll
    for (int i = 0; i < 8; i++) if (i < w) wo += ws[i];
    int excl = wo + v - cnt;
#pragma unroll
    for (int i = 0; i < 8; i++) {
        g_slot[b * SS + base + i] = loc[i] ? excl : -1;
        excl += loc[i];
    }
    if (t == 255) {
        int tot = wo + v;
        g_nvalid[b] = tot;
        g_npad[b]   = (tot + 127) & ~127;
    }
}

// gather compacted X rows (fp16): 8 rows per block, 512 halves = 64 uint4/row
__global__ void __launch_bounds__(256)
gather_x() {
    const int r = blockIdx.x * 8 + (threadIdx.x >> 5);
    const int lane = threadIdx.x & 31;
    const int slot = g_slot[r];
    if (slot < 0) return;
    const int b = r >> 11;
    const uint4* s = reinterpret_cast<const uint4*>(g_x16 + (size_t)r * DD);
    uint4* d = reinterpret_cast<uint4*>(g_x16c + ((size_t)b * SS + slot) * DD);
    d[lane] = s[lane]; d[lane + 32] = s[lane + 32];
}

// merged QKV (all fp16 2-pass): grid=(4,128,3).
// z=0: Q over all rows; z=1: K (fp16 split, compacted); z=2: V^T (fp16 split)
__global__ void __launch_bounds__(256, 2)
qkv_mm(int dummy) {
    extern __shared__ char smem[];
    const int z = blockIdx.z;
    int m0, b = 0;
    const __half* A;
    if (z == 0) {
        m0 = blockIdx.y * 128;
        A = g_x16;
    } else {
        b = blockIdx.y >> 4;
        m0 = (blockIdx.y & 15) * 128;
        if (m0 >= g_npad[b]) return;
        A = g_x16c + (size_t)b * SS * DD;
    }
    const int n0 = blockIdx.x * 128;
    const __half* Wh = g_w16h + z * DD * DD;
    const __half* Wl = g_w16l + z * DD * DD;

    float acc[2][8][4];
    gemm_pipe_f16(A, Wh, Wl, DD, DD, DD, m0, n0, smem, acc);

    const int lane = threadIdx.x & 31;
    const int w = threadIdx.x >> 5;
    const int wm = w & 3, wn = w >> 2;
    const int mb = m0 + wm * 32 + (lane >> 2);
    const int nb = n0 + wn * 64 + (lane & 3) * 2;

    if (z == 0) {
#pragma unroll
        for (int mi = 0; mi < 2; mi++) {
            int m = mb + mi * 16;
#pragma unroll
            for (int nj = 0; nj < 8; nj++) {
                int n = nb + nj * 8;
                *reinterpret_cast<uint32_t*>(g_q16 + (size_t)m * DD + n) =
                    pack_h2(acc[mi][nj][0], acc[mi][nj][1]);
                *reinterpret_cast<uint32_t*>(g_q16 + (size_t)(m + 8) * DD + n) =
                    pack_h2(acc[mi][nj][2], acc[mi][nj][3]);
            }
        }
    } else if (z == 1) {
        __half* kh = g_k16h + (size_t)b * SS * DD;
        __half* kl = g_k16l + (size_t)b * SS * DD;
#pragma unroll
        for (int mi = 0; mi < 2; mi++) {
#pragma unroll
            for (int half = 0; half < 2; half++) {
                int m = mb + mi * 16 + half * 8;
#pragma unroll
                for (int nj = 0; nj < 8; nj++) {
                    int n = nb + nj * 8;
                    float a = acc[mi][nj][half * 2], c = acc[mi][nj][half * 2 + 1];
                    *reinterpret_cast<uint32_t*>(kh + (size_t)m * DD + n) = pack_h2(a, c);
                    *reinterpret_cast<uint32_t*>(kl + (size_t)m * DD + n) =
                        pack_h2(a - hfv(a), c - hfv(c));
                }
            }
        }
    } else {
        __half* vh = g_vt16h + (size_t)b * DD * SS;
        __half* vl = g_vt16l + (size_t)b * DD * SS;
#pragma unroll
        for (int mi = 0; mi < 2; mi++) {
#pragma unroll
            for (int half = 0; half < 2; half++) {
                int s = mb + mi * 16 + half * 8;
#pragma unroll
                for (int nj = 0; nj < 8; nj++) {
                    int d = nb + nj * 8;
                    float v0 = acc[mi][nj][half * 2];
                    float v1 = acc[mi][nj][half * 2 + 1];
                    vh[(size_t)d * SS + s]       = __float2half(v0);
                    vl[(size_t)d * SS + s]       = __float2half(v0 - hfv(v0));
                    vh[(size_t)(d + 1) * SS + s] = __float2half(v1);
                    vl[(size_t)(d + 1) * SS + s] = __float2half(v1 - hfv(v1));
                }
            }
        }
    }
}

// scores: fp16 2-pass over compacted keys. grid=(16,16,8)
__global__ void __launch_bounds__(256, 2)
scores_mm(int dummy) {
    extern __shared__ char smem[];
    const int b = blockIdx.z;
    const int npad = g_npad[b];
    if (blockIdx.x * 128 >= npad) return;
    const int nv = g_nvalid[b];
    const int m0 = blockIdx.y * 128, n0 = blockIdx.x * 128;

    float acc[2][8][4];
    gemm_pipe_f16(g_q16 + (size_t)b * SS * DD,
                  g_k16h + (size_t)b * SS * DD, g_k16l + (size_t)b * SS * DD,
                  DD, DD, DD, m0, n0, smem, acc);

    const int lane = threadIdx.x & 31;
    const int w = threadIdx.x >> 5;
    const int wm = w & 3, wn = w >> 2;
    const int mb = m0 + wm * 32 + (lane >> 2);
    const int nb = n0 + wn * 64 + (lane & 3) * 2;
    const float inv_scale = 0.0220970869120796101f;  // 1/sqrt(2048)
    float* Scb = g_sc + (size_t)b * SS * SS;

#pragma unroll
    for (int nj = 0; nj < 8; nj++) {
        int n = nb + nj * 8;
#pragma unroll
        for (int mi = 0; mi < 2; mi++) {
            int m = mb + mi * 16;
            float r0 = (n     < nv) ? acc[mi][nj][0] * inv_scale : -1e30f;
            float r1 = (n + 1 < nv) ? acc[mi][nj][1] * inv_scale : -1e30f;
            float r2 = (n     < nv) ? acc[mi][nj][2] * inv_scale : -1e30f;
            float r3 = (n + 1 < nv) ? acc[mi][nj][3] * inv_scale : -1e30f;
            *reinterpret_cast<float2*>(Scb + (size_t)m * SS + n) = make_float2(r0, r1);
            *reinterpret_cast<float2*>(Scb + (size_t)(m + 8) * SS + n) = make_float2(r2, r3);
        }
    }
}

// softmax over compacted width -> plain fp16 P
__global__ void __launch_bounds__(256)
softmax_kernel() {
    __shared__ float red[8];
    const int b = blockIdx.x >> 11;
    const int W = g_npad[b];
    const size_t base = (size_t)blockIdx.x * SS;
    const float* p = g_sc + base;
    const int tid = threadIdx.x;

    float4 v[2];
    int ni = 0;
    float mx = -1e38f;
    for (int x = tid * 4; x < W; x += 1024) {
        v[ni] = *reinterpret_cast<const float4*>(p + x);
        mx = fmaxf(mx, fmaxf(fmaxf(v[ni].x, v[ni].y), fmaxf(v[ni].z, v[ni].w)));
        ni++;
    }
#pragma unroll
    for (int o = 16; o > 0; o >>= 1) mx = fmaxf(mx, __shfl_xor_sync(0xffffffffu, mx, o));
    if ((tid & 31) == 0) red[tid >> 5] = mx;
    __syncthreads();
    mx = red[0];
#pragma unroll
    for (int wi = 1; wi < 8; wi++) mx = fmaxf(mx, red[wi]);

    float sum = 0.0f;
    for (int i = 0; i < ni; i++) {
        v[i].x = __expf(v[i].x - mx);
        v[i].y = __expf(v[i].y - mx);
        v[i].z = __expf(v[i].z - mx);
        v[i].w = __expf(v[i].w - mx);
        sum += (v[i].x + v[i].y) + (v[i].z + v[i].w);
    }
#pragma unroll
    for (int o = 16; o > 0; o >>= 1) sum += __shfl_xor_sync(0xffffffffu, sum, o);
    __syncthreads();
    if ((tid & 31) == 0) red[tid >> 5] = sum;
    __syncthreads();
    sum = 0.0f;
#pragma unroll
    for (int wi = 0; wi < 8; wi++) sum += red[wi];

    const float rinv = 1.0f / sum;
    int i = 0;
    for (int x = tid * 4; x < W; x += 1024, i++) {
        *reinterpret_cast<uint2*>(g_p16 + base + x) =
            make_uint2(pack_h2(v[i].x * rinv, v[i].y * rinv),
                       pack_h2(v[i].z * rinv, v[i].w * rinv));
    }
}

// PV (fp16 2-pass) over compacted K-dim: grid=(4,16,8)
__global__ void __launch_bounds__(256, 2)
pv_mm(float* __restrict__ out) {
    extern __shared__ char smem[];
    const int b = blockIdx.z;
    const int W = g_npad[b];
    const int m0 = blockIdx.y * 128, n0 = blockIdx.x * 128;
    float acc[2][8][4];
    gemm_pipe_f16(g_p16 + (size_t)b * SS * SS,
                  g_vt16h + (size_t)b * DD * SS, g_vt16l + (size_t)b * DD * SS,
                  W, SS, SS, m0, n0, smem, acc);

    const int lane = threadIdx.x & 31;
    const int w = threadIdx.x >> 5;
    const int wm = w & 3, wn = w >> 2;
    const int mb = m0 + wm * 32 + (lane >> 2);
    const int nb = n0 + wn * 64 + (lane & 3) * 2;
    float* C = out + (size_t)b * SS * DD;
#pragma unroll
    for (int mi = 0; mi < 2; mi++) {
        int m = mb + mi * 16;
#pragma unroll
        for (int nj = 0; nj < 8; nj++) {
            int n = nb + nj * 8;
            *reinterpret_cast<float2*>(C + (size_t)m * DD + n) =
                make_float2(acc[mi][nj][0], acc[mi][nj][1]);
            *reinterpret_cast<float2*>(C + (size_t)(m + 8) * DD + n) =
                make_float2(acc[mi][nj][2], acc[mi][nj][3]);
        }
    }
}

// ---------------------------------------------------------------------------
extern "C" void kernel_launch(void* const* d_in, const int* in_sizes, int n_in,
                              void* d_out, int out_size) {
    const float* X    = (const float*)d_in[0];
    const int*   mask = (const int*)  d_in[1];
    const float* Wq   = (const float*)d_in[2];
    const float* Wk   = (const float*)d_in[3];
    const float* Wv   = (const float*)d_in[4];
    float* out = (float*)d_out;

    static bool attr_done = false;
    if (!attr_done) {
        cudaFuncSetAttribute(qkv_mm,    cudaFuncAttributeMaxDynamicSharedMemorySize, SMEM_BYTES);
        cudaFuncSetAttribute(scores_mm, cudaFuncAttributeMaxDynamicSharedMemorySize, SMEM_BYTES);
        cudaFuncSetAttribute(pv_mm,     cudaFuncAttributeMaxDynamicSharedMemorySize, SMEM_BYTES);
        attr_done = true;
    }

    __half *x16, *wh, *wl;
    cudaGetSymbolAddress((void**)&x16, g_x16);
    cudaGetSymbolAddress((void**)&wh,  g_w16h);
    cudaGetSymbolAddress((void**)&wl,  g_w16l);

    const int nX4 = (BB * SS * DD) / 4;
    const int nW4 = (DD * DD) / 4;
    split_plain<<<(nX4 + 255) / 256, 256>>>(X, x16, nX4);
    split_f16<<<(nW4 + 255) / 256, 256>>>(Wq, wh,            wl,            nW4);
    split_f16<<<(nW4 + 255) / 256, 256>>>(Wk, wh + DD * DD,  wl + DD * DD,  nW4);
    split_f16<<<(nW4 + 255) / 256, 256>>>(Wv, wh + 2*DD*DD,  wl + 2*DD*DD,  nW4);
    build_index<<<BB, 256>>>(mask);
    gather_x<<<BB * SS / 8, 256>>>();

    dim3 blk(256);
    qkv_mm<<<dim3(DD / 128, 128, 3), blk, SMEM_BYTES>>>(0);
    scores_mm<<<dim3(SS / 128, SS / 128, BB), blk, SMEM_BYTES>>>(0);
    softmax_kernel<<<BB * SS, 256>>>();
    pv_mm<<<dim3(DD / 128, SS / 128, BB), blk, SMEM_BYTES>>>(out);
}

// round 13
// speedup vs baseline: 2.0401x; 1.2670x over previous
#include <cuda_runtime.h>
#include <cuda_fp16.h>
#include <cstdint>

#define BB 8
#define SS 2048
#define DD 512

// ---------------- device-global scratch (allocation-free) -------------------
__device__ __align__(16) __half g_x16 [(size_t)BB * SS * DD];  // X plain fp16
__device__ __align__(16) __half g_x16c[(size_t)BB * SS * DD];  // compacted X
__device__ __align__(16) __half g_w16 [3 * DD * DD];           // W plain fp16
__device__ __align__(16) __half g_q16 [(size_t)BB * SS * DD];  // Q plain fp16 (unscaled)
__device__ __align__(16) __half g_k16 [(size_t)BB * SS * DD];  // K plain fp16, compacted
__device__ __align__(16) __half g_vt16h[(size_t)BB * DD * SS]; // V^T fp16 split [b][d][slot]
__device__ __align__(16) __half g_vt16l[(size_t)BB * DD * SS];
__device__ __align__(16) float  g_sc [(size_t)BB * SS * SS];
__device__ __align__(16) __half g_p16[(size_t)BB * SS * SS];   // P plain fp16
__device__ int g_slot[BB * SS];
__device__ int g_nvalid[BB];
__device__ int g_npad[BB];

// ---------------- PTX helpers ----------------------------------------------
static __device__ __forceinline__ uint32_t su32(const void* p) {
    return (uint32_t)__cvta_generic_to_shared(p);
}
__device__ __forceinline__ void cp16(uint32_t dst, const void* src) {
    asm volatile("cp.async.cg.shared.global [%0], [%1], 16;" :: "r"(dst), "l"(src));
}
__device__ __forceinline__ void cp_commit() {
    asm volatile("cp.async.commit_group;" ::: "memory");
}
template <int N>
__device__ __forceinline__ void cp_wait() {
    asm volatile("cp.async.wait_group %0;" :: "n"(N) : "memory");
}
__device__ __forceinline__ void ldm_x4(uint32_t addr, uint32_t r[4]) {
    asm volatile("ldmatrix.sync.aligned.m8n8.x4.shared.b16 {%0,%1,%2,%3}, [%4];"
                 : "=r"(r[0]), "=r"(r[1]), "=r"(r[2]), "=r"(r[3]) : "r"(addr));
}
__device__ __forceinline__ void mma_f16(float c[4], const uint32_t a[4], const uint32_t b[2]) {
    asm volatile(
        "mma.sync.aligned.m16n8k16.row.col.f32.f16.f16.f32 "
        "{%0,%1,%2,%3}, {%4,%5,%6,%7}, {%8,%9}, {%0,%1,%2,%3};"
        : "+f"(c[0]), "+f"(c[1]), "+f"(c[2]), "+f"(c[3])
        : "r"(a[0]), "r"(a[1]), "r"(a[2]), "r"(a[3]), "r"(b[0]), "r"(b[1]));
}
__device__ __forceinline__ uint32_t pack_h2(float a, float b) {
    __half2 t(__float2half(a), __float2half(b));
    return *reinterpret_cast<uint32_t*>(&t);
}
__device__ __forceinline__ float hfv(float a) {
    return __half2float(__float2half(a));
}

// ---------------- shared GEMM constants --------------------------------------
#define PITCH 48
#define TILE_B 6144            // 128 * 48
#define NSTG 4

// ---------------- single-pass fp16 GEMM: C = A * B^T -------------------------
// Stage = {A, B} tiles of 128x16 fp16 at 48B pitch.
#define STAGE1_B 12288          // 2 * TILE_B
#define SMEM1_BYTES (NSTG * STAGE1_B)   // 49152

__device__ __forceinline__ void gemm_1p(const __half* __restrict__ Ag,
                                        const __half* __restrict__ Bg,
                                        int K, int ldA, int ldB,
                                        int m0, int n0,
                                        char* smem, float acc[2][8][4]) {
    const int tid  = threadIdx.x;
    const int lane = tid & 31;
    const int w    = tid >> 5;
    const int wm   = w & 3;
    const int wn   = w >> 2;
    const uint32_t sbase = su32(smem);

#pragma unroll
    for (int mi = 0; mi < 2; mi++)
#pragma unroll
        for (int nj = 0; nj < 8; nj++)
#pragma unroll
            for (int e = 0; e < 4; e++) acc[mi][nj][e] = 0.0f;

    const int NK = K >> 4;
    const int r0 = tid >> 1;
    const int c0 = tid & 1;

    const uint32_t offA = (uint32_t)(wm * 32 + (lane & 15)) * PITCH + ((lane >> 4) * 8) * 2;
    const uint32_t offB = (uint32_t)(wn * 64 + (lane & 7) + ((lane >> 4) << 3)) * PITCH
                        + (((lane >> 3) & 1) << 3) * 2;

#define ISSUE1(kidx)                                                              \
    do {                                                                          \
        const int k0 = (kidx) << 4;                                               \
        uint32_t st = sbase + ((kidx) & (NSTG - 1)) * STAGE1_B;                   \
        size_t ga = (size_t)(m0 + r0) * ldA + k0 + c0 * 8;                        \
        size_t gb = (size_t)(n0 + r0) * ldB + k0 + c0 * 8;                        \
        uint32_t da = st + r0 * PITCH + c0 * 16;                                  \
        cp16(da,          Ag + ga);                                               \
        cp16(da + TILE_B, Bg + gb);                                               \
        cp_commit();                                                              \
    } while (0)

    ISSUE1(0); ISSUE1(1); ISSUE1(2);

    for (int k = 0; k < NK; k++) {
        cp_wait<2>();
        __syncthreads();

        const uint32_t st = sbase + (k & (NSTG - 1)) * STAGE1_B;
        uint32_t ah[2][4];
#pragma unroll
        for (int mi = 0; mi < 2; mi++)
            ldm_x4(st + offA + (uint32_t)(mi * 16 * PITCH), ah[mi]);
        uint32_t bh[8][2];
#pragma unroll
        for (int nj4 = 0; nj4 < 4; nj4++) {
            uint32_t t[4];
            ldm_x4(st + TILE_B + offB + (uint32_t)(nj4 * 16 * PITCH), t);
            bh[2 * nj4][0] = t[0]; bh[2 * nj4][1] = t[1];
            bh[2 * nj4 + 1][0] = t[2]; bh[2 * nj4 + 1][1] = t[3];
        }

#pragma unroll
        for (int mi = 0; mi < 2; mi++)
#pragma unroll
            for (int nj = 0; nj < 8; nj++)
                mma_f16(acc[mi][nj], ah[mi], bh[nj]);

        if (k + 3 < NK) ISSUE1(k + 3);
        else            cp_commit();
    }
#undef ISSUE1
}

// ---------------- 2-pass fp16 GEMM: C = A * (Bh+Bl)^T (for PV) ---------------
#define STAGE2_B 18432          // 3 * TILE_B
#define SMEM2_BYTES (NSTG * STAGE2_B)   // 73728

__device__ __forceinline__ void gemm_2p(const __half* __restrict__ Ag,
                                        const __half* __restrict__ Bgh,
                                        const __half* __restrict__ Bgl,
                                        int K, int ldA, int ldB,
                                        int m0, int n0,
                                        char* smem, float acc[2][8][4]) {
    const int tid  = threadIdx.x;
    const int lane = tid & 31;
    const int w    = tid >> 5;
    const int wm   = w & 3;
    const int wn   = w >> 2;
    const uint32_t sbase = su32(smem);

#pragma unroll
    for (int mi = 0; mi < 2; mi++)
#pragma unroll
        for (int nj = 0; nj < 8; nj++)
#pragma unroll
            for (int e = 0; e < 4; e++) acc[mi][nj][e] = 0.0f;

    const int NK = K >> 4;
    const int r0 = tid >> 1;
    const int c0 = tid & 1;

    const uint32_t offA = (uint32_t)(wm * 32 + (lane & 15)) * PITCH + ((lane >> 4) * 8) * 2;
    const uint32_t offB = (uint32_t)(wn * 64 + (lane & 7) + ((lane >> 4) << 3)) * PITCH
                        + (((lane >> 3) & 1) << 3) * 2;

#define ISSUE2(kidx)                                                              \
    do {                                                                          \
        const int k0 = (kidx) << 4;                                               \
        uint32_t st = sbase + ((kidx) & (NSTG - 1)) * STAGE2_B;                   \
        size_t ga = (size_t)(m0 + r0) * ldA + k0 + c0 * 8;                        \
        size_t gb = (size_t)(n0 + r0) * ldB + k0 + c0 * 8;                        \
        uint32_t da = st + r0 * PITCH + c0 * 16;                                  \
        cp16(da,              Ag  + ga);                                          \
        cp16(da + TILE_B,     Bgh + gb);                                          \
        cp16(da + 2 * TILE_B, Bgl + gb);                                          \
        cp_commit();                                                              \
    } while (0)

    ISSUE2(0); ISSUE2(1); ISSUE2(2);

    for (int k = 0; k < NK; k++) {
        cp_wait<2>();
        __syncthreads();

        const uint32_t st  = sbase + (k & (NSTG - 1)) * STAGE2_B;
        uint32_t ah[2][4];
#pragma unroll
        for (int mi = 0; mi < 2; mi++)
            ldm_x4(st + offA + (uint32_t)(mi * 16 * PITCH), ah[mi]);
        uint32_t bh[8][2], bl[8][2];
#pragma unroll
        for (int nj4 = 0; nj4 < 4; nj4++) {
            uint32_t o = offB + (uint32_t)(nj4 * 16 * PITCH);
            uint32_t t[4];
            ldm_x4(st + TILE_B + o, t);
            bh[2 * nj4][0] = t[0]; bh[2 * nj4][1] = t[1];
            bh[2 * nj4 + 1][0] = t[2]; bh[2 * nj4 + 1][1] = t[3];
            ldm_x4(st + 2 * TILE_B + o, t);
            bl[2 * nj4][0] = t[0]; bl[2 * nj4][1] = t[1];
            bl[2 * nj4 + 1][0] = t[2]; bl[2 * nj4 + 1][1] = t[3];
        }

#pragma unroll
        for (int mi = 0; mi < 2; mi++)
#pragma unroll
            for (int nj = 0; nj < 8; nj++)
                mma_f16(acc[mi][nj], ah[mi], bh[nj]);
#pragma unroll
        for (int mi = 0; mi < 2; mi++)
#pragma unroll
            for (int nj = 0; nj < 8; nj++)
                mma_f16(acc[mi][nj], ah[mi], bl[nj]);

        if (k + 3 < NK) ISSUE2(k + 3);
        else            cp_commit();
    }
#undef ISSUE2
}

// ---------------- kernels ----------------------------------------------------
// fused convert: X and all 3 W matrices -> plain fp16, one launch
#define NX4 ((BB * SS * DD) / 4)   // 2097152
#define NW4 ((DD * DD) / 4)        // 65536
__global__ void __launch_bounds__(256)
convert_all(const float* __restrict__ X, const float* __restrict__ Wq,
            const float* __restrict__ Wk, const float* __restrict__ Wv) {
    int i = blockIdx.x * blockDim.x + threadIdx.x;
    const float* src;
    __half* dst;
    int j;
    if (i < NX4) {
        src = X; dst = g_x16; j = i;
    } else {
        int i2 = i - NX4;
        int wsel = i2 / NW4;
        j = i2 - wsel * NW4;
        if (wsel >= 3) return;
        src = (wsel == 0) ? Wq : ((wsel == 1) ? Wk : Wv);
        dst = g_w16 + (size_t)wsel * DD * DD;
    }
    float4 v = reinterpret_cast<const float4*>(src)[j];
    reinterpret_cast<uint2*>(dst)[j] = make_uint2(pack_h2(v.x, v.y), pack_h2(v.z, v.w));
}

__global__ void __launch_bounds__(256)
build_index(const int* __restrict__ mask) {
    const int b = blockIdx.x;
    const int t = threadIdx.x;
    const int* m = mask + b * SS;
    const int base = t * 8;
    int loc[8], cnt = 0;
#pragma unroll
    for (int i = 0; i < 8; i++) { loc[i] = (m[base + i] != 0); cnt += loc[i]; }
    const int lane = t & 31, w = t >> 5;
    int v = cnt;
#pragma unroll
    for (int o = 1; o < 32; o <<= 1) {
        int u = __shfl_up_sync(0xffffffffu, v, o);
        if (lane >= o) v += u;
    }
    __shared__ int ws[8];
    if (lane == 31) ws[w] = v;
    __syncthreads();
    int wo = 0;
#pragma unroll
    for (int i = 0; i < 8; i++) if (i < w) wo += ws[i];
    int excl = wo + v - cnt;
#pragma unroll
    for (int i = 0; i < 8; i++) {
        g_slot[b * SS + base + i] = loc[i] ? excl : -1;
        excl += loc[i];
    }
    if (t == 255) {
        int tot = wo + v;
        g_nvalid[b] = tot;
        g_npad[b]   = (tot + 127) & ~127;
    }
}

__global__ void __launch_bounds__(256)
gather_x() {
    const int r = blockIdx.x * 8 + (threadIdx.x >> 5);
    const int lane = threadIdx.x & 31;
    const int slot = g_slot[r];
    if (slot < 0) return;
    const int b = r >> 11;
    const uint4* s = reinterpret_cast<const uint4*>(g_x16 + (size_t)r * DD);
    uint4* d = reinterpret_cast<uint4*>(g_x16c + ((size_t)b * SS + slot) * DD);
    d[lane] = s[lane]; d[lane + 32] = s[lane + 32];
}

// merged QKV, all single-pass fp16: grid=(4,128,3).
// z=0: Q over all rows; z=1: K plain compacted; z=2: V^T fp16-split compacted
__global__ void __launch_bounds__(256, 2)
qkv_mm(int dummy) {
    extern __shared__ char smem[];
    const int z = blockIdx.z;
    int m0, b = 0;
    const __half* A;
    if (z == 0) {
        m0 = blockIdx.y * 128;
        A = g_x16;
    } else {
        b = blockIdx.y >> 4;
        m0 = (blockIdx.y & 15) * 128;
        if (m0 >= g_npad[b]) return;
        A = g_x16c + (size_t)b * SS * DD;
    }
    const int n0 = blockIdx.x * 128;

    float acc[2][8][4];
    gemm_1p(A, g_w16 + (size_t)z * DD * DD, DD, DD, DD, m0, n0, smem, acc);

    const int lane = threadIdx.x & 31;
    const int w = threadIdx.x >> 5;
    const int wm = w & 3, wn = w >> 2;
    const int mb = m0 + wm * 32 + (lane >> 2);
    const int nb = n0 + wn * 64 + (lane & 3) * 2;

    if (z == 0) {
#pragma unroll
        for (int mi = 0; mi < 2; mi++) {
            int m = mb + mi * 16;
#pragma unroll
            for (int nj = 0; nj < 8; nj++) {
                int n = nb + nj * 8;
                *reinterpret_cast<uint32_t*>(g_q16 + (size_t)m * DD + n) =
                    pack_h2(acc[mi][nj][0], acc[mi][nj][1]);
                *reinterpret_cast<uint32_t*>(g_q16 + (size_t)(m + 8) * DD + n) =
                    pack_h2(acc[mi][nj][2], acc[mi][nj][3]);
            }
        }
    } else if (z == 1) {
        __half* kk = g_k16 + (size_t)b * SS * DD;
#pragma unroll
        for (int mi = 0; mi < 2; mi++) {
            int m = mb + mi * 16;
#pragma unroll
            for (int nj = 0; nj < 8; nj++) {
                int n = nb + nj * 8;
                *reinterpret_cast<uint32_t*>(kk + (size_t)m * DD + n) =
                    pack_h2(acc[mi][nj][0], acc[mi][nj][1]);
                *reinterpret_cast<uint32_t*>(kk + (size_t)(m + 8) * DD + n) =
                    pack_h2(acc[mi][nj][2], acc[mi][nj][3]);
            }
        }
    } else {
        __half* vh = g_vt16h + (size_t)b * DD * SS;
        __half* vl = g_vt16l + (size_t)b * DD * SS;
#pragma unroll
        for (int mi = 0; mi < 2; mi++) {
#pragma unroll
            for (int half = 0; half < 2; half++) {
                int s = mb + mi * 16 + half * 8;
#pragma unroll
                for (int nj = 0; nj < 8; nj++) {
                    int d = nb + nj * 8;
                    float v0 = acc[mi][nj][half * 2];
                    float v1 = acc[mi][nj][half * 2 + 1];
                    vh[(size_t)d * SS + s]       = __float2half(v0);
                    vl[(size_t)d * SS + s]       = __float2half(v0 - hfv(v0));
                    vh[(size_t)(d + 1) * SS + s] = __float2half(v1);
                    vl[(size_t)(d + 1) * SS + s] = __float2half(v1 - hfv(v1));
                }
            }
        }
    }
}

// scores: single-pass fp16 over compacted keys. grid=(16,16,8)
__global__ void __launch_bounds__(256, 2)
scores_mm(int dummy) {
    extern __shared__ char smem[];
    const int b = blockIdx.z;
    const int npad = g_npad[b];
    if (blockIdx.x * 128 >= npad) return;
    const int nv = g_nvalid[b];
    const int m0 = blockIdx.y * 128, n0 = blockIdx.x * 128;

    float acc[2][8][4];
    gemm_1p(g_q16 + (size_t)b * SS * DD, g_k16 + (size_t)b * SS * DD,
            DD, DD, DD, m0, n0, smem, acc);

    const int lane = threadIdx.x & 31;
    const int w = threadIdx.x >> 5;
    const int wm = w & 3, wn = w >> 2;
    const int mb = m0 + wm * 32 + (lane >> 2);
    const int nb = n0 + wn * 64 + (lane & 3) * 2;
    const float inv_scale = 0.0220970869120796101f;  // 1/sqrt(2048)
    float* Scb = g_sc + (size_t)b * SS * SS;

#pragma unroll
    for (int nj = 0; nj < 8; nj++) {
        int n = nb + nj * 8;
#pragma unroll
        for (int mi = 0; mi < 2; mi++) {
            int m = mb + mi * 16;
            float r0 = (n     < nv) ? acc[mi][nj][0] * inv_scale : -1e30f;
            float r1 = (n + 1 < nv) ? acc[mi][nj][1] * inv_scale : -1e30f;
            float r2 = (n     < nv) ? acc[mi][nj][2] * inv_scale : -1e30f;
            float r3 = (n + 1 < nv) ? acc[mi][nj][3] * inv_scale : -1e30f;
            *reinterpret_cast<float2*>(Scb + (size_t)m * SS + n) = make_float2(r0, r1);
            *reinterpret_cast<float2*>(Scb + (size_t)(m + 8) * SS + n) = make_float2(r2, r3);
        }
    }
}

// softmax over compacted width -> plain fp16 P
__global__ void __launch_bounds__(256)
softmax_kernel() {
    __shared__ float red[8];
    const int b = blockIdx.x >> 11;
    const int W = g_npad[b];
    const size_t base = (size_t)blockIdx.x * SS;
    const float* p = g_sc + base;
    const int tid = threadIdx.x;

    float4 v[2];
    int ni = 0;
    float mx = -1e38f;
    for (int x = tid * 4; x < W; x += 1024) {
        v[ni] = *reinterpret_cast<const float4*>(p + x);
        mx = fmaxf(mx, fmaxf(fmaxf(v[ni].x, v[ni].y), fmaxf(v[ni].z, v[ni].w)));
        ni++;
    }
#pragma unroll
    for (int o = 16; o > 0; o >>= 1) mx = fmaxf(mx, __shfl_xor_sync(0xffffffffu, mx, o));
    if ((tid & 31) == 0) red[tid >> 5] = mx;
    __syncthreads();
    mx = red[0];
#pragma unroll
    for (int wi = 1; wi < 8; wi++) mx = fmaxf(mx, red[wi]);

    float sum = 0.0f;
    for (int i = 0; i < ni; i++) {
        v[i].x = __expf(v[i].x - mx);
        v[i].y = __expf(v[i].y - mx);
        v[i].z = __expf(v[i].z - mx);
        v[i].w = __expf(v[i].w - mx);
        sum += (v[i].x + v[i].y) + (v[i].z + v[i].w);
    }
#pragma unroll
    for (int o = 16; o > 0; o >>= 1) sum += __shfl_xor_sync(0xffffffffu, sum, o);
    __syncthreads();
    if ((tid & 31) == 0) red[tid >> 5] = sum;
    __syncthreads();
    sum = 0.0f;
#pragma unroll
    for (int wi = 0; wi < 8; wi++) sum += red[wi];

    const float rinv = 1.0f / sum;
    int i = 0;
    for (int x = tid * 4; x < W; x += 1024, i++) {
        *reinterpret_cast<uint2*>(g_p16 + base + x) =
            make_uint2(pack_h2(v[i].x * rinv, v[i].y * rinv),
                       pack_h2(v[i].z * rinv, v[i].w * rinv));
    }
}

// PV (fp16 2-pass) over compacted K-dim: grid=(4,16,8)
__global__ void __launch_bounds__(256, 2)
pv_mm(float* __restrict__ out) {
    extern __shared__ char smem[];
    const int b = blockIdx.z;
    const int W = g_npad[b];
    const int m0 = blockIdx.y * 128, n0 = blockIdx.x * 128;
    float acc[2][8][4];
    gemm_2p(g_p16 + (size_t)b * SS * SS,
            g_vt16h + (size_t)b * DD * SS, g_vt16l + (size_t)b * DD * SS,
            W, SS, SS, m0, n0, smem, acc);

    const int lane = threadIdx.x & 31;
    const int w = threadIdx.x >> 5;
    const int wm = w & 3, wn = w >> 2;
    const int mb = m0 + wm * 32 + (lane >> 2);
    const int nb = n0 + wn * 64 + (lane & 3) * 2;
    float* C = out + (size_t)b * SS * DD;
#pragma unroll
    for (int mi = 0; mi < 2; mi++) {
        int m = mb + mi * 16;
#pragma unroll
        for (int nj = 0; nj < 8; nj++) {
            int n = nb + nj * 8;
            *reinterpret_cast<float2*>(C + (size_t)m * DD + n) =
                make_float2(acc[mi][nj][0], acc[mi][nj][1]);
            *reinterpret_cast<float2*>(C + (size_t)(m + 8) * DD + n) =
                make_float2(acc[mi][nj][2], acc[mi][nj][3]);
        }
    }
}

// ---------------------------------------------------------------------------
extern "C" void kernel_launch(void* const* d_in, const int* in_sizes, int n_in,
                              void* d_out, int out_size) {
    const float* X    = (const float*)d_in[0];
    const int*   mask = (const int*)  d_in[1];
    const float* Wq   = (const float*)d_in[2];
    const float* Wk   = (const float*)d_in[3];
    const float* Wv   = (const float*)d_in[4];
    float* out = (float*)d_out;

    static bool attr_done = false;
    if (!attr_done) {
        cudaFuncSetAttribute(qkv_mm,    cudaFuncAttributeMaxDynamicSharedMemorySize, SMEM1_BYTES);
        cudaFuncSetAttribute(scores_mm, cudaFuncAttributeMaxDynamicSharedMemorySize, SMEM1_BYTES);
        cudaFuncSetAttribute(pv_mm,     cudaFuncAttributeMaxDynamicSharedMemorySize, SMEM2_BYTES);
        attr_done = true;
    }

    const int nconv = NX4 + 3 * NW4;
    convert_all<<<(nconv + 255) / 256, 256>>>(X, Wq, Wk, Wv);
    build_index<<<BB, 256>>>(mask);
    gather_x<<<BB * SS / 8, 256>>>();

    dim3 blk(256);
    qkv_mm<<<dim3(DD / 128, 128, 3), blk, SMEM1_BYTES>>>(0);
    scores_mm<<<dim3(SS / 128, SS / 128, BB), blk, SMEM1_BYTES>>>(0);
    softmax_kernel<<<BB * SS, 256>>>();
    pv_mm<<<dim3(DD / 128, SS / 128, BB), blk, SMEM2_BYTES>>>(out);
}

// round 14
// speedup vs baseline: 2.5312x; 1.2407x over previous
#include <cuda_runtime.h>
#include <cuda_fp16.h>
#include <cstdint>

#define BB 8
#define SS 2048
#define DD 512

// ---------------- device-global scratch (allocation-free) -------------------
__device__ __align__(16) __half g_x16 [(size_t)BB * SS * DD];  // X plain fp16
__device__ __align__(16) __half g_x16c[(size_t)BB * SS * DD];  // compacted X
__device__ __align__(16) __half g_w16 [3 * DD * DD];           // W plain fp16
__device__ __align__(16) __half g_q16 [(size_t)BB * SS * DD];  // Q plain fp16 (unscaled)
__device__ __align__(16) __half g_k16 [(size_t)BB * SS * DD];  // K plain fp16, compacted
__device__ __align__(16) __half g_vt16[(size_t)BB * DD * SS];  // V^T plain fp16 [b][d][slot]
__device__ __align__(16) __half g_p16 [(size_t)BB * SS * SS];  // logits -> probs (in place)
__device__ int g_slot[BB * SS];
__device__ int g_nvalid[BB];
__device__ int g_npad[BB];

// ---------------- PTX helpers ----------------------------------------------
static __device__ __forceinline__ uint32_t su32(const void* p) {
    return (uint32_t)__cvta_generic_to_shared(p);
}
__device__ __forceinline__ void cp16(uint32_t dst, const void* src) {
    asm volatile("cp.async.cg.shared.global [%0], [%1], 16;" :: "r"(dst), "l"(src));
}
__device__ __forceinline__ void cp_commit() {
    asm volatile("cp.async.commit_group;" ::: "memory");
}
template <int N>
__device__ __forceinline__ void cp_wait() {
    asm volatile("cp.async.wait_group %0;" :: "n"(N) : "memory");
}
__device__ __forceinline__ void ldm_x4(uint32_t addr, uint32_t r[4]) {
    asm volatile("ldmatrix.sync.aligned.m8n8.x4.shared.b16 {%0,%1,%2,%3}, [%4];"
                 : "=r"(r[0]), "=r"(r[1]), "=r"(r[2]), "=r"(r[3]) : "r"(addr));
}
__device__ __forceinline__ void mma_f16(float c[4], const uint32_t a[4], const uint32_t b[2]) {
    asm volatile(
        "mma.sync.aligned.m16n8k16.row.col.f32.f16.f16.f32 "
        "{%0,%1,%2,%3}, {%4,%5,%6,%7}, {%8,%9}, {%0,%1,%2,%3};"
        : "+f"(c[0]), "+f"(c[1]), "+f"(c[2]), "+f"(c[3])
        : "r"(a[0]), "r"(a[1]), "r"(a[2]), "r"(a[3]), "r"(b[0]), "r"(b[1]));
}
__device__ __forceinline__ uint32_t pack_h2(float a, float b) {
    __half2 t(__float2half(a), __float2half(b));
    return *reinterpret_cast<uint32_t*>(&t);
}

// ---------------- single-pass fp16 pipelined GEMM: C = A * B^T ---------------
#define PITCH 48
#define TILE_B 6144            // 128 * 48
#define NSTG 4
#define STAGE1_B 12288          // 2 * TILE_B
#define SMEM1_BYTES (NSTG * STAGE1_B)   // 49152

__device__ __forceinline__ void gemm_1p(const __half* __restrict__ Ag,
                                        const __half* __restrict__ Bg,
                                        int K, int ldA, int ldB,
                                        int m0, int n0,
                                        char* smem, float acc[2][8][4]) {
    const int tid  = threadIdx.x;
    const int lane = tid & 31;
    const int w    = tid >> 5;
    const int wm   = w & 3;
    const int wn   = w >> 2;
    const uint32_t sbase = su32(smem);

#pragma unroll
    for (int mi = 0; mi < 2; mi++)
#pragma unroll
        for (int nj = 0; nj < 8; nj++)
#pragma unroll
            for (int e = 0; e < 4; e++) acc[mi][nj][e] = 0.0f;

    const int NK = K >> 4;
    const int r0 = tid >> 1;
    const int c0 = tid & 1;

    const uint32_t offA = (uint32_t)(wm * 32 + (lane & 15)) * PITCH + ((lane >> 4) * 8) * 2;
    const uint32_t offB = (uint32_t)(wn * 64 + (lane & 7) + ((lane >> 4) << 3)) * PITCH
                        + (((lane >> 3) & 1) << 3) * 2;

#define ISSUE1(kidx)                                                              \
    do {                                                                          \
        const int k0 = (kidx) << 4;                                               \
        uint32_t st = sbase + ((kidx) & (NSTG - 1)) * STAGE1_B;                   \
        size_t ga = (size_t)(m0 + r0) * ldA + k0 + c0 * 8;                        \
        size_t gb = (size_t)(n0 + r0) * ldB + k0 + c0 * 8;                        \
        uint32_t da = st + r0 * PITCH + c0 * 16;                                  \
        cp16(da,          Ag + ga);                                               \
        cp16(da + TILE_B, Bg + gb);                                               \
        cp_commit();                                                              \
    } while (0)

    ISSUE1(0); ISSUE1(1); ISSUE1(2);

    for (int k = 0; k < NK; k++) {
        cp_wait<2>();
        __syncthreads();

        const uint32_t st = sbase + (k & (NSTG - 1)) * STAGE1_B;
        uint32_t ah[2][4];
#pragma unroll
        for (int mi = 0; mi < 2; mi++)
            ldm_x4(st + offA + (uint32_t)(mi * 16 * PITCH), ah[mi]);
        uint32_t bh[8][2];
#pragma unroll
        for (int nj4 = 0; nj4 < 4; nj4++) {
            uint32_t t[4];
            ldm_x4(st + TILE_B + offB + (uint32_t)(nj4 * 16 * PITCH), t);
            bh[2 * nj4][0] = t[0]; bh[2 * nj4][1] = t[1];
            bh[2 * nj4 + 1][0] = t[2]; bh[2 * nj4 + 1][1] = t[3];
        }

#pragma unroll
        for (int mi = 0; mi < 2; mi++)
#pragma unroll
            for (int nj = 0; nj < 8; nj++)
                mma_f16(acc[mi][nj], ah[mi], bh[nj]);

        if (k + 3 < NK) ISSUE1(k + 3);
        else            cp_commit();
    }
#undef ISSUE1
}

// ---------------- kernels ----------------------------------------------------
#define NX4 ((BB * SS * DD) / 4)
#define NW4 ((DD * DD) / 4)
__global__ void __launch_bounds__(256)
convert_all(const float* __restrict__ X, const float* __restrict__ Wq,
            const float* __restrict__ Wk, const float* __restrict__ Wv) {
    int i = blockIdx.x * blockDim.x + threadIdx.x;
    const float* src;
    __half* dst;
    int j;
    if (i < NX4) {
        src = X; dst = g_x16; j = i;
    } else {
        int i2 = i - NX4;
        int wsel = i2 / NW4;
        j = i2 - wsel * NW4;
        if (wsel >= 3) return;
        src = (wsel == 0) ? Wq : ((wsel == 1) ? Wk : Wv);
        dst = g_w16 + (size_t)wsel * DD * DD;
    }
    float4 v = reinterpret_cast<const float4*>(src)[j];
    reinterpret_cast<uint2*>(dst)[j] = make_uint2(pack_h2(v.x, v.y), pack_h2(v.z, v.w));
}

__global__ void __launch_bounds__(256)
build_index(const int* __restrict__ mask) {
    const int b = blockIdx.x;
    const int t = threadIdx.x;
    const int* m = mask + b * SS;
    const int base = t * 8;
    int loc[8], cnt = 0;
#pragma unroll
    for (int i = 0; i < 8; i++) { loc[i] = (m[base + i] != 0); cnt += loc[i]; }
    const int lane = t & 31, w = t >> 5;
    int v = cnt;
#pragma unroll
    for (int o = 1; o < 32; o <<= 1) {
        int u = __shfl_up_sync(0xffffffffu, v, o);
        if (lane >= o) v += u;
    }
    __shared__ int ws[8];
    if (lane == 31) ws[w] = v;
    __syncthreads();
    int wo = 0;
#pragma unroll
    for (int i = 0; i < 8; i++) if (i < w) wo += ws[i];
    int excl = wo + v - cnt;
#pragma unroll
    for (int i = 0; i < 8; i++) {
        g_slot[b * SS + base + i] = loc[i] ? excl : -1;
        excl += loc[i];
    }
    if (t == 255) {
        int tot = wo + v;
        g_nvalid[b] = tot;
        g_npad[b]   = (tot + 127) & ~127;
    }
}

__global__ void __launch_bounds__(256)
gather_x() {
    const int r = blockIdx.x * 8 + (threadIdx.x >> 5);
    const int lane = threadIdx.x & 31;
    const int slot = g_slot[r];
    if (slot < 0) return;
    const int b = r >> 11;
    const uint4* s = reinterpret_cast<const uint4*>(g_x16 + (size_t)r * DD);
    uint4* d = reinterpret_cast<uint4*>(g_x16c + ((size_t)b * SS + slot) * DD);
    d[lane] = s[lane]; d[lane + 32] = s[lane + 32];
}

// merged QKV, single-pass fp16: grid=(4,128,3).
__global__ void __launch_bounds__(256, 2)
qkv_mm(int dummy) {
    extern __shared__ char smem[];
    const int z = blockIdx.z;
    int m0, b = 0;
    const __half* A;
    if (z == 0) {
        m0 = blockIdx.y * 128;
        A = g_x16;
    } else {
        b = blockIdx.y >> 4;
        m0 = (blockIdx.y & 15) * 128;
        if (m0 >= g_npad[b]) return;
        A = g_x16c + (size_t)b * SS * DD;
    }
    const int n0 = blockIdx.x * 128;

    float acc[2][8][4];
    gemm_1p(A, g_w16 + (size_t)z * DD * DD, DD, DD, DD, m0, n0, smem, acc);

    const int lane = threadIdx.x & 31;
    const int w = threadIdx.x >> 5;
    const int wm = w & 3, wn = w >> 2;
    const int mb = m0 + wm * 32 + (lane >> 2);
    const int nb = n0 + wn * 64 + (lane & 3) * 2;

    if (z == 0) {
#pragma unroll
        for (int mi = 0; mi < 2; mi++) {
            int m = mb + mi * 16;
#pragma unroll
            for (int nj = 0; nj < 8; nj++) {
                int n = nb + nj * 8;
                *reinterpret_cast<uint32_t*>(g_q16 + (size_t)m * DD + n) =
                    pack_h2(acc[mi][nj][0], acc[mi][nj][1]);
                *reinterpret_cast<uint32_t*>(g_q16 + (size_t)(m + 8) * DD + n) =
                    pack_h2(acc[mi][nj][2], acc[mi][nj][3]);
            }
        }
    } else if (z == 1) {
        __half* kk = g_k16 + (size_t)b * SS * DD;
#pragma unroll
        for (int mi = 0; mi < 2; mi++) {
            int m = mb + mi * 16;
#pragma unroll
            for (int nj = 0; nj < 8; nj++) {
                int n = nb + nj * 8;
                *reinterpret_cast<uint32_t*>(kk + (size_t)m * DD + n) =
                    pack_h2(acc[mi][nj][0], acc[mi][nj][1]);
                *reinterpret_cast<uint32_t*>(kk + (size_t)(m + 8) * DD + n) =
                    pack_h2(acc[mi][nj][2], acc[mi][nj][3]);
            }
        }
    } else {
        __half* vt = g_vt16 + (size_t)b * DD * SS;
#pragma unroll
        for (int mi = 0; mi < 2; mi++) {
#pragma unroll
            for (int half = 0; half < 2; half++) {
                int s = mb + mi * 16 + half * 8;
#pragma unroll
                for (int nj = 0; nj < 8; nj++) {
                    int d = nb + nj * 8;
                    vt[(size_t)d * SS + s]       = __float2half(acc[mi][nj][half * 2]);
                    vt[(size_t)(d + 1) * SS + s] = __float2half(acc[mi][nj][half * 2 + 1]);
                }
            }
        }
    }
}

// scores: single-pass fp16, writes fp16 logits to g_p16. grid=(16,16,8)
__global__ void __launch_bounds__(256, 2)
scores_mm(int dummy) {
    extern __shared__ char smem[];
    const int b = blockIdx.z;
    const int npad = g_npad[b];
    if (blockIdx.x * 128 >= npad) return;
    const int nv = g_nvalid[b];
    const int m0 = blockIdx.y * 128, n0 = blockIdx.x * 128;

    float acc[2][8][4];
    gemm_1p(g_q16 + (size_t)b * SS * DD, g_k16 + (size_t)b * SS * DD,
            DD, DD, DD, m0, n0, smem, acc);

    const int lane = threadIdx.x & 31;
    const int w = threadIdx.x >> 5;
    const int wm = w & 3, wn = w >> 2;
    const int mb = m0 + wm * 32 + (lane >> 2);
    const int nb = n0 + wn * 64 + (lane & 3) * 2;
    const float inv_scale = 0.0220970869120796101f;  // 1/sqrt(2048)
    __half* Pb = g_p16 + (size_t)b * SS * SS;

#pragma unroll
    for (int nj = 0; nj < 8; nj++) {
        int n = nb + nj * 8;
#pragma unroll
        for (int mi = 0; mi < 2; mi++) {
            int m = mb + mi * 16;
            float r0 = (n     < nv) ? acc[mi][nj][0] * inv_scale : -65504.0f;
            float r1 = (n + 1 < nv) ? acc[mi][nj][1] * inv_scale : -65504.0f;
            float r2 = (n     < nv) ? acc[mi][nj][2] * inv_scale : -65504.0f;
            float r3 = (n + 1 < nv) ? acc[mi][nj][3] * inv_scale : -65504.0f;
            *reinterpret_cast<uint32_t*>(Pb + (size_t)m * SS + n)       = pack_h2(r0, r1);
            *reinterpret_cast<uint32_t*>(Pb + (size_t)(m + 8) * SS + n) = pack_h2(r2, r3);
        }
    }
}

// softmax in place over fp16 logits -> fp16 probs. one block per (b,row)
__global__ void __launch_bounds__(256)
softmax_kernel() {
    __shared__ float red[8];
    const int b = blockIdx.x >> 11;
    const int W = g_npad[b];
    const size_t base = (size_t)blockIdx.x * SS;
    __half* p = g_p16 + base;
    const int tid = threadIdx.x;

    // W <= 2048: each thread owns one uint4 (8 halves)
    float v[8];
    const int x0 = tid * 8;
    bool active = (x0 < W);
    float mx = -1e30f;
    if (active) {
        uint4 u = *reinterpret_cast<const uint4*>(p + x0);
        const __half* hp = reinterpret_cast<const __half*>(&u);
#pragma unroll
        for (int i = 0; i < 8; i++) {
            v[i] = __half2float(hp[i]);
            mx = fmaxf(mx, v[i]);
        }
    }
#pragma unroll
    for (int o = 16; o > 0; o >>= 1) mx = fmaxf(mx, __shfl_xor_sync(0xffffffffu, mx, o));
    if ((tid & 31) == 0) red[tid >> 5] = mx;
    __syncthreads();
    mx = red[0];
#pragma unroll
    for (int wi = 1; wi < 8; wi++) mx = fmaxf(mx, red[wi]);

    float sum = 0.0f;
    if (active) {
#pragma unroll
        for (int i = 0; i < 8; i++) {
            v[i] = __expf(v[i] - mx);
            sum += v[i];
        }
    }
#pragma unroll
    for (int o = 16; o > 0; o >>= 1) sum += __shfl_xor_sync(0xffffffffu, sum, o);
    __syncthreads();
    if ((tid & 31) == 0) red[tid >> 5] = sum;
    __syncthreads();
    sum = 0.0f;
#pragma unroll
    for (int wi = 0; wi < 8; wi++) sum += red[wi];

    if (active) {
        const float rinv = 1.0f / sum;
        uint4 o;
        uint32_t* ow = reinterpret_cast<uint32_t*>(&o);
#pragma unroll
        for (int i = 0; i < 4; i++)
            ow[i] = pack_h2(v[2 * i] * rinv, v[2 * i + 1] * rinv);
        *reinterpret_cast<uint4*>(p + x0) = o;
    }
}

// PV single-pass fp16 over compacted K-dim: grid=(4,16,8)
__global__ void __launch_bounds__(256, 2)
pv_mm(float* __restrict__ out) {
    extern __shared__ char smem[];
    const int b = blockIdx.z;
    const int W = g_npad[b];
    const int m0 = blockIdx.y * 128, n0 = blockIdx.x * 128;
    float acc[2][8][4];
    gemm_1p(g_p16 + (size_t)b * SS * SS, g_vt16 + (size_t)b * DD * SS,
            W, SS, SS, m0, n0, smem, acc);

    const int lane = threadIdx.x & 31;
    const int w = threadIdx.x >> 5;
    const int wm = w & 3, wn = w >> 2;
    const int mb = m0 + wm * 32 + (lane >> 2);
    const int nb = n0 + wn * 64 + (lane & 3) * 2;
    float* C = out + (size_t)b * SS * DD;
#pragma unroll
    for (int mi = 0; mi < 2; mi++) {
        int m = mb + mi * 16;
#pragma unroll
        for (int nj = 0; nj < 8; nj++) {
            int n = nb + nj * 8;
            *reinterpret_cast<float2*>(C + (size_t)m * DD + n) =
                make_float2(acc[mi][nj][0], acc[mi][nj][1]);
            *reinterpret_cast<float2*>(C + (size_t)(m + 8) * DD + n) =
                make_float2(acc[mi][nj][2], acc[mi][nj][3]);
        }
    }
}

// ---------------------------------------------------------------------------
extern "C" void kernel_launch(void* const* d_in, const int* in_sizes, int n_in,
                              void* d_out, int out_size) {
    const float* X    = (const float*)d_in[0];
    const int*   mask = (const int*)  d_in[1];
    const float* Wq   = (const float*)d_in[2];
    const float* Wk   = (const float*)d_in[3];
    const float* Wv   = (const float*)d_in[4];
    float* out = (float*)d_out;

    static bool attr_done = false;
    if (!attr_done) {
        cudaFuncSetAttribute(qkv_mm,    cudaFuncAttributeMaxDynamicSharedMemorySize, SMEM1_BYTES);
        cudaFuncSetAttribute(scores_mm, cudaFuncAttributeMaxDynamicSharedMemorySize, SMEM1_BYTES);
        cudaFuncSetAttribute(pv_mm,     cudaFuncAttributeMaxDynamicSharedMemorySize, SMEM1_BYTES);
        attr_done = true;
    }

    const int nconv = NX4 + 3 * NW4;
    convert_all<<<(nconv + 255) / 256, 256>>>(X, Wq, Wk, Wv);
    build_index<<<BB, 256>>>(mask);
    gather_x<<<BB * SS / 8, 256>>>();

    dim3 blk(256);
    qkv_mm<<<dim3(DD / 128, 128, 3), blk, SMEM1_BYTES>>>(0);
    scores_mm<<<dim3(SS / 128, SS / 128, BB), blk, SMEM1_BYTES>>>(0);
    softmax_kernel<<<BB * SS, 256>>>();
    pv_mm<<<dim3(DD / 128, SS / 128, BB), blk, SMEM1_BYTES>>>(out);
}